// round 3
// baseline (speedup 1.0000x reference)
#include <cuda_runtime.h>
#include <math.h>

// Problem constants
constexpr int BB = 16;    // batch
constexpr int LL = 512;   // seq len
constexpr int DD = 768;   // hidden
constexpr int HH = 4;     // heads
constexpr int AA = 100;   // attn dim
constexpr int DKk = 25;   // head dim
constexpr int PP = 3;     // classes
constexpr float EPSf = 1e-6f;
constexpr int TI = 16;    // query rows per attention block

// ------------------- device scratch (allowed: __device__ globals) -------------------
__device__ float g_seq_ln[BB * LL * DD];        // 24 MB
__device__ float g_feats [BB * LL * 3 * AA];    // x | xg1 | xg2  (ld = 300)
__device__ float g_q     [BB * LL * AA];
__device__ float g_k     [BB * LL * AA];
__device__ float g_adj   [BB * HH * LL * LL];   // 64 MB
__device__ float g_adj2  [BB * HH * LL * LL];   // 64 MB
__device__ float g_Ax    [BB * LL * AA];
__device__ float g_u     [BB * LL * HH];
__device__ float g_v     [BB * LL * HH];
__device__ float g_node  [BB * LL * AA];
__device__ float g_pooled[BB * AA];

// ------------------- LayerNorm (ddof=1, eps added to std) -------------------
__global__ void ln_kernel(const float* __restrict__ x,
                          const float* __restrict__ ga,
                          const float* __restrict__ gb,
                          float* __restrict__ out)
{
    int row = blockIdx.x;                 // b*L + l
    const float* xr = x + (size_t)row * DD;
    float s = 0.f, s2 = 0.f;
    for (int d = threadIdx.x; d < DD; d += 256) {
        float v = xr[d];
        s += v;
        s2 = fmaf(v, v, s2);
    }
    __shared__ float sha[8], shb[8];
    for (int o = 16; o; o >>= 1) {
        s  += __shfl_down_sync(0xffffffffu, s,  o);
        s2 += __shfl_down_sync(0xffffffffu, s2, o);
    }
    if ((threadIdx.x & 31) == 0) { sha[threadIdx.x >> 5] = s; shb[threadIdx.x >> 5] = s2; }
    __syncthreads();
    float ts = 0.f, ts2 = 0.f;
#pragma unroll
    for (int w = 0; w < 8; w++) { ts += sha[w]; ts2 += shb[w]; }
    float mean = ts / (float)DD;
    float var  = (ts2 - (float)DD * mean * mean) / (float)(DD - 1);
    float inv  = 1.f / (sqrtf(fmaxf(var, 0.f)) + EPSf);
    float* orow = out + (size_t)row * DD;
    for (int d = threadIdx.x; d < DD; d += 256)
        orow[d] = ga[d] * (xr[d] - mean) * inv + gb[d];
}

// ------------------- generic GEMM: C = A(MxK,lda) * W^T(NxK,ldw) + bias, opt relu ---
// 64x64 tile, 16x16 threads, 4x4 micro-tile (strided, conflict-free)
__global__ void gemm_nt(const float* __restrict__ Am, int lda,
                        const float* __restrict__ Wm, int ldw,
                        const float* __restrict__ bias,
                        float* __restrict__ Cm, int ldc,
                        int M, int N, int K, int relu_flag)
{
    __shared__ float As[16][65];
    __shared__ float Ws[16][65];
    int bm = blockIdx.y * 64;
    int bn = blockIdx.x * 64;
    int tx = threadIdx.x, ty = threadIdx.y;
    int tid = ty * 16 + tx;
    float acc[4][4] = {};
    for (int k0 = 0; k0 < K; k0 += 16) {
#pragma unroll
        for (int e = tid; e < 64 * 16; e += 256) {
            int r = e >> 4, c = e & 15;
            int gr = bm + r, gc = k0 + c;
            As[c][r] = (gr < M && gc < K) ? Am[(size_t)gr * lda + gc] : 0.f;
        }
#pragma unroll
        for (int e = tid; e < 64 * 16; e += 256) {
            int r = e >> 4, c = e & 15;
            int gr = bn + r, gc = k0 + c;
            Ws[c][r] = (gr < N && gc < K) ? Wm[(size_t)gr * ldw + gc] : 0.f;
        }
        __syncthreads();
#pragma unroll
        for (int kk = 0; kk < 16; kk++) {
            float a[4], w[4];
#pragma unroll
            for (int i = 0; i < 4; i++) a[i] = As[kk][i * 16 + ty];
#pragma unroll
            for (int j = 0; j < 4; j++) w[j] = Ws[kk][j * 16 + tx];
#pragma unroll
            for (int i = 0; i < 4; i++)
#pragma unroll
                for (int j = 0; j < 4; j++)
                    acc[i][j] = fmaf(a[i], w[j], acc[i][j]);
        }
        __syncthreads();
    }
#pragma unroll
    for (int i = 0; i < 4; i++) {
        int row = bm + i * 16 + ty;
        if (row >= M) continue;
#pragma unroll
        for (int j = 0; j < 4; j++) {
            int col = bn + j * 16 + tx;
            if (col >= N) continue;
            float v = acc[i][j] + (bias ? bias[col] : 0.f);
            if (relu_flag) v = fmaxf(v, 0.f);
            Cm[(size_t)row * ldc + col] = v;
        }
    }
}

// ------------------- fused attention: scores + mask + syntax + softmax ---------------
// one block per (b, h, 16-row i-tile); full K tile (512x25) staged in dyn smem
__global__ void attn_kernel(const float* __restrict__ q,
                            const float* __restrict__ k,
                            const float* __restrict__ syn,
                            const int* __restrict__ src_mask,
                            float* __restrict__ adj)
{
    extern __shared__ float ks[];   // LL*DKk floats = 51200 B
    __shared__ float qs[DKk];
    __shared__ float red[8];
    int blk = blockIdx.x;
    int itile = blk % (LL / TI);
    int h = (blk / (LL / TI)) % HH;
    int b = blk / ((LL / TI) * HH);
    int tid = threadIdx.x;   // 256

    for (int e = tid; e < LL * DKk; e += 256) {
        int j = e / DKk, d = e % DKk;
        ks[e] = k[((size_t)(b * LL + j)) * AA + h * DKk + d];
    }
    __syncthreads();

    for (int ii = 0; ii < TI; ii++) {
        int i = itile * TI + ii;
        if (tid < DKk) qs[tid] = q[((size_t)(b * LL + i)) * AA + h * DKk + tid];
        __syncthreads();
        size_t rowoff = ((size_t)((b * HH + h) * LL + i)) * LL;

        float v0, v1;
        float m = -1e30f;
#pragma unroll
        for (int t = 0; t < 2; t++) {
            int j = tid + t * 256;
            const float* kr = ks + j * DKk;
            float dot = 0.f;
#pragma unroll
            for (int d = 0; d < DKk; d++) dot = fmaf(qs[d], kr[d], dot);
            float s = src_mask[b * LL + j] ? dot * 0.2f : -1e9f;
            s += syn[rowoff + j];
            if (t == 0) v0 = s; else v1 = s;
            m = fmaxf(m, s);
        }
        // block max
        for (int o = 16; o; o >>= 1) m = fmaxf(m, __shfl_xor_sync(0xffffffffu, m, o));
        if ((tid & 31) == 0) red[tid >> 5] = m;
        __syncthreads();
        m = red[0];
#pragma unroll
        for (int w = 1; w < 8; w++) m = fmaxf(m, red[w]);
        __syncthreads();   // protect red before reuse

        float e0 = expf(v0 - m), e1 = expf(v1 - m);
        float s = e0 + e1;
        for (int o = 16; o; o >>= 1) s += __shfl_xor_sync(0xffffffffu, s, o);
        if ((tid & 31) == 0) red[tid >> 5] = s;
        __syncthreads();
        float tot = 0.f;
#pragma unroll
        for (int w = 0; w < 8; w++) tot += red[w];
        float inv = 1.f / tot;
        adj[rowoff + tid]       = e0 * inv;
        adj[rowoff + tid + 256] = e1 * inv;
        __syncthreads();   // protect qs/red before next row
    }
}

// ------------------- Ax = (1/H) * (sum_h adj_h) @ X   (batched NN, 64x128 tile) -----
__global__ void ax_kernel(const float* __restrict__ adj,
                          const float* __restrict__ X, int ldx,
                          float* __restrict__ out)
{
    __shared__ float As[16][65];     // adjsum tile: [j][i]
    __shared__ float Bs[16][128];    // X tile: [j][d]
    int b  = blockIdx.z;
    int bi = blockIdx.y * 64;
    int tx = threadIdx.x, ty = threadIdx.y;
    int tid = ty * 16 + tx;
    float acc[4][8] = {};
    const float* adjb = adj + (size_t)b * HH * LL * LL;
    const float* Xb   = X + (size_t)b * LL * ldx;
    for (int k0 = 0; k0 < LL; k0 += 16) {
#pragma unroll
        for (int e = tid; e < 64 * 16; e += 256) {
            int r = e >> 4, c = e & 15;
            size_t off = (size_t)(bi + r) * LL + (k0 + c);
            float s = adjb[off] + adjb[off + (size_t)LL * LL]
                    + adjb[off + 2 * (size_t)LL * LL] + adjb[off + 3 * (size_t)LL * LL];
            As[c][r] = s;
        }
#pragma unroll
        for (int e = tid; e < 16 * 128; e += 256) {
            int r = e >> 7, c = e & 127;
            Bs[r][c] = (c < AA) ? Xb[(size_t)(k0 + r) * ldx + c] : 0.f;
        }
        __syncthreads();
#pragma unroll
        for (int kk = 0; kk < 16; kk++) {
            float a[4], xv[8];
#pragma unroll
            for (int i = 0; i < 4; i++) a[i] = As[kk][i * 16 + ty];
#pragma unroll
            for (int j = 0; j < 8; j++) xv[j] = Bs[kk][j * 16 + tx];
#pragma unroll
            for (int i = 0; i < 4; i++)
#pragma unroll
                for (int j = 0; j < 8; j++)
                    acc[i][j] = fmaf(a[i], xv[j], acc[i][j]);
        }
        __syncthreads();
    }
#pragma unroll
    for (int i = 0; i < 4; i++) {
        int row = bi + i * 16 + ty;
#pragma unroll
        for (int j = 0; j < 8; j++) {
            int d = j * 16 + tx;
            if (d < AA)
                out[((size_t)b * LL + row) * AA + d] = acc[i][j] * 0.25f;
        }
    }
}

// ------------------- adj rewiring: e_adj + u + v + bias -------------------
__global__ void adj_update_kernel(const float* __restrict__ adj,
                                  const float* __restrict__ Wx_w,
                                  const float* __restrict__ Wx_b,
                                  const float* __restrict__ u,
                                  const float* __restrict__ v,
                                  float* __restrict__ out)
{
    size_t idx = (size_t)blockIdx.x * blockDim.x + threadIdx.x;
    if (idx >= (size_t)BB * LL * LL) return;
    int j = (int)(idx % LL);
    int i = (int)((idx / LL) % LL);
    int b = (int)(idx / ((size_t)LL * LL));
    size_t base = ((size_t)b * HH * LL + i) * LL + j;   // h=0 slot
    float av[HH];
#pragma unroll
    for (int h = 0; h < HH; h++) av[h] = adj[base + (size_t)h * LL * LL];
#pragma unroll
    for (int g = 0; g < HH; g++) {
        float s = __ldg(&Wx_b[g]);
#pragma unroll
        for (int h = 0; h < HH; h++)
            s = fmaf(__ldg(&Wx_w[g * (HH + 2 * AA) + h]), av[h], s);
        s += u[(b * LL + j) * HH + g] + v[(b * LL + i) * HH + g];
        out[base + (size_t)g * LL * LL] = s;
    }
}

// ------------------- masked mean pool -------------------
__global__ void pool_kernel(const float* __restrict__ node,
                            const int* __restrict__ mask_ids,
                            float* __restrict__ pooled)
{
    int b = blockIdx.x;
    int tid = threadIdx.x;
    __shared__ int sred[8];
    int ms = 0;
    for (int l = tid; l < LL; l += 256) ms += mask_ids[b * LL + l];
    for (int o = 16; o; o >>= 1) ms += __shfl_xor_sync(0xffffffffu, ms, o);
    if ((tid & 31) == 0) sred[tid >> 5] = ms;
    __syncthreads();
    int tot = 0;
#pragma unroll
    for (int w = 0; w < 8; w++) tot += sred[w];
    float inv = 1.f / fmaxf((float)tot, 1.f);
    for (int d = tid; d < AA; d += 256) {
        float s = 0.f;
        for (int l = 0; l < LL; l++)
            s += node[((size_t)(b * LL + l)) * AA + d];
        pooled[b * AA + d] = s * inv;
    }
}

// ------------------- logits -------------------
__global__ void logits_kernel(const float* __restrict__ pooled,
                              const float* __restrict__ cls_w,
                              const float* __restrict__ cls_b,
                              float* __restrict__ out)
{
    int t = threadIdx.x;
    if (t >= BB * PP) return;
    int b = t / PP, p = t % PP;
    float s = cls_b[p];
    for (int d = 0; d < AA; d++)
        s = fmaf(pooled[b * AA + d], cls_w[p * AA + d], s);
    out[t] = s;
}

// ------------------- launch -------------------
extern "C" void kernel_launch(void* const* d_in, const int* in_sizes, int n_in,
                              void* d_out, int out_size)
{
    const float* seq     = (const float*)d_in[0];
    const float* syn     = (const float*)d_in[1];
    const float* ln_a    = (const float*)d_in[2];
    const float* ln_b    = (const float*)d_in[3];
    const float* Wxx_w   = (const float*)d_in[4];
    const float* Wxx_b   = (const float*)d_in[5];
    const float* q_w     = (const float*)d_in[6];
    const float* q_b     = (const float*)d_in[7];
    const float* k_w     = (const float*)d_in[8];
    const float* k_b     = (const float*)d_in[9];
    const float* W_w     = (const float*)d_in[10];
    const float* W_b     = (const float*)d_in[11];
    const float* Wx_w    = (const float*)d_in[12];
    const float* Wx_b    = (const float*)d_in[13];
    const float* agg_w   = (const float*)d_in[14];
    const float* agg_b   = (const float*)d_in[15];
    const float* cls_w   = (const float*)d_in[16];
    const float* cls_b   = (const float*)d_in[17];
    const int*   mask_ids= (const int*)d_in[18];
    const int*   src_mask= (const int*)d_in[19];
    float* out = (float*)d_out;

    float *seq_ln, *feats, *q, *k, *adj, *adj2, *Ax, *u, *v, *node, *pooled;
    cudaGetSymbolAddress((void**)&seq_ln, g_seq_ln);
    cudaGetSymbolAddress((void**)&feats,  g_feats);
    cudaGetSymbolAddress((void**)&q,      g_q);
    cudaGetSymbolAddress((void**)&k,      g_k);
    cudaGetSymbolAddress((void**)&adj,    g_adj);
    cudaGetSymbolAddress((void**)&adj2,   g_adj2);
    cudaGetSymbolAddress((void**)&Ax,     g_Ax);
    cudaGetSymbolAddress((void**)&u,      g_u);
    cudaGetSymbolAddress((void**)&v,      g_v);
    cudaGetSymbolAddress((void**)&node,   g_node);
    cudaGetSymbolAddress((void**)&pooled, g_pooled);

    dim3 thr(16, 16);
    const int M = BB * LL;          // 8192
    const int LDF = 3 * AA;         // 300

    // 1) LayerNorm
    ln_kernel<<<M, 256>>>(seq, ln_a, ln_b, seq_ln);
    // 2) x = seq_ln @ Wxx^T + b  -> feats[:, 0:100]
    gemm_nt<<<dim3(2, 128), thr>>>(seq_ln, DD, Wxx_w, DD, Wxx_b, feats, LDF, M, AA, DD, 0);
    // 3) q, k
    gemm_nt<<<dim3(2, 128), thr>>>(feats, LDF, q_w, AA, q_b, q, AA, M, AA, AA, 0);
    gemm_nt<<<dim3(2, 128), thr>>>(feats, LDF, k_w, AA, k_b, k, AA, M, AA, AA, 0);
    // 4) fused attention -> adj (softmax)
    const int ATTN_SMEM = LL * DKk * (int)sizeof(float);   // 51200 B
    cudaFuncSetAttribute(attn_kernel, cudaFuncAttributeMaxDynamicSharedMemorySize, ATTN_SMEM);
    attn_kernel<<<BB * HH * (LL / TI), 256, ATTN_SMEM>>>(q, k, syn, src_mask, adj);
    // 5) GCN layer 1
    ax_kernel<<<dim3(1, LL / 64, BB), thr>>>(adj, feats, LDF, Ax);
    gemm_nt<<<dim3(2, 128), thr>>>(Ax, AA, W_w, AA, W_b, feats + AA, LDF, M, AA, AA, 1);
    gemm_nt<<<dim3(1, 128), thr>>>(feats + AA, LDF, Wx_w + HH,      HH + 2 * AA, nullptr, u, HH, M, HH, AA, 0);
    gemm_nt<<<dim3(1, 128), thr>>>(feats + AA, LDF, Wx_w + HH + AA, HH + 2 * AA, nullptr, v, HH, M, HH, AA, 0);
    adj_update_kernel<<<(BB * LL * LL) / 256, 256>>>(adj, Wx_w, Wx_b, u, v, adj2);
    // 6) GCN layer 2 (final adj update is dead code -> skipped)
    ax_kernel<<<dim3(1, LL / 64, BB), thr>>>(adj2, feats + AA, LDF, Ax);
    gemm_nt<<<dim3(2, 128), thr>>>(Ax, AA, W_w, AA, W_b, feats + 2 * AA, LDF, M, AA, AA, 1);
    // 7) aggregate: node = relu(feats @ agg_w^T + b)
    gemm_nt<<<dim3(2, 128), thr>>>(feats, LDF, agg_w, LDF, agg_b, node, AA, M, AA, LDF, 1);
    // 8) pool + 9) logits
    pool_kernel<<<BB, 256>>>(node, mask_ids, pooled);
    logits_kernel<<<1, 64>>>(pooled, cls_w, cls_b, out);
}

// round 5
// speedup vs baseline: 1.5632x; 1.5632x over previous
#include <cuda_runtime.h>
#include <math.h>

constexpr int BB = 16, LL = 512, DD = 768, HH = 4, AA = 100, DKk = 25, PP = 3;
constexpr int LDF = 3 * AA;            // 300
constexpr int LDW_X = HH + 2 * AA;     // 204
constexpr float EPSf = 1e-6f;

// ---------------- device scratch ----------------
__device__ float g_feats [BB * LL * LDF];       // x | x1 | x2
__device__ float g_q     [BB * LL * AA];
__device__ float g_k     [BB * LL * AA];
__device__ float g_P1    [BB * LL * LL];        // sum_h adj_h          (16 MB)
__device__ float g_Pc    [BB * LL * LL];        // sum_h c_h adj_h      (16 MB)
__device__ float g_Ax    [BB * LL * AA];
__device__ float g_U     [BB * LL];
__device__ float g_V     [BB * LL];
__device__ float g_corrS [BB * 2 * AA];         // per b: corr[100], S[100]
__device__ float g_pre   [256];                 // c[4], b1s[100], b2s[100], Cb
__device__ float g_pool  [BB * AA];             // pooled raw sums
__device__ float g_mean  [BB * LL];
__device__ float g_inv   [BB * LL];

// ---------------- precompute: c, b1s, b2s, Cb + zero pool ----------------
__global__ void precomp_kernel(const float* __restrict__ Wxw,
                               const float* __restrict__ Wxb,
                               float* __restrict__ pre, float* __restrict__ pool)
{
    int t = threadIdx.x;
    if (t < 4) {
        float s = 0.f;
        for (int g = 0; g < HH; g++) s += Wxw[g * LDW_X + t];
        pre[t] = s;
    } else if (t < 104) {
        int d = t - 4; float s = 0.f;
        for (int g = 0; g < HH; g++) s += Wxw[g * LDW_X + HH + d];
        pre[t] = s;
    } else if (t < 204) {
        int d = t - 104; float s = 0.f;
        for (int g = 0; g < HH; g++) s += Wxw[g * LDW_X + HH + AA + d];
        pre[t] = s;
    } else if (t == 204) {
        pre[204] = Wxb[0] + Wxb[1] + Wxb[2] + Wxb[3];
    }
    for (int e = t; e < BB * AA; e += 256) pool[e] = 0.f;
}

// ---------------- LN stats (one warp per row) ----------------
__global__ void ln_stats(const float* __restrict__ x,
                         float* __restrict__ mean, float* __restrict__ inv)
{
    int row = blockIdx.x * 8 + (threadIdx.x >> 5);
    int lane = threadIdx.x & 31;
    const float* xr = x + (size_t)row * DD;
    float s = 0.f, s2 = 0.f;
    for (int d = lane; d < DD; d += 32) { float v = xr[d]; s += v; s2 = fmaf(v, v, s2); }
    for (int o = 16; o; o >>= 1) {
        s  += __shfl_xor_sync(0xffffffffu, s,  o);
        s2 += __shfl_xor_sync(0xffffffffu, s2, o);
    }
    if (lane == 0) {
        float m   = s / (float)DD;
        float var = (s2 - (float)DD * m * m) / (float)(DD - 1);
        mean[row] = m;
        inv[row]  = 1.f / (sqrtf(fmaxf(var, 0.f)) + EPSf);
    }
}

// ---------------- Wxx GEMM with fused LayerNorm --------------------------
// C[M x 100] = LN(seq)[M x 768] @ W^T(100 x 768) + bias;  BM=64 BN=128 BK=32
__global__ void gemm_ln(const float* __restrict__ seq,
                        const float* __restrict__ ga, const float* __restrict__ gb,
                        const float* __restrict__ mean, const float* __restrict__ inv,
                        const float* __restrict__ W, const float* __restrict__ bias,
                        float* __restrict__ C)
{
    __shared__ float As[32][65];
    __shared__ float Ws[32][129];
    __shared__ float rmean[64], rinv[64];
    int bm = blockIdx.x * 64;
    int tx = threadIdx.x & 15, ty = threadIdx.x >> 4;
    int tid = threadIdx.x;
    if (tid < 64) { rmean[tid] = mean[bm + tid]; rinv[tid] = inv[bm + tid]; }
    __syncthreads();
    float acc[4][8] = {};
    for (int k0 = 0; k0 < DD; k0 += 32) {
#pragma unroll
        for (int e = tid; e < 64 * 32; e += 256) {
            int m = e >> 5, kk = e & 31;
            int kc = k0 + kk;
            float v = seq[(size_t)(bm + m) * DD + kc];
            As[kk][m] = fmaf(__ldg(&ga[kc]), (v - rmean[m]) * rinv[m], __ldg(&gb[kc]));
        }
#pragma unroll
        for (int e = tid; e < 128 * 32; e += 256) {
            int n = e >> 5, kk = e & 31;
            Ws[kk][n] = (n < AA) ? W[(size_t)n * DD + k0 + kk] : 0.f;
        }
        __syncthreads();
#pragma unroll
        for (int kk = 0; kk < 32; kk++) {
            float a[4], w[8];
#pragma unroll
            for (int i = 0; i < 4; i++) a[i] = As[kk][ty + 16 * i];
#pragma unroll
            for (int j = 0; j < 8; j++) w[j] = Ws[kk][tx + 16 * j];
#pragma unroll
            for (int i = 0; i < 4; i++)
#pragma unroll
                for (int j = 0; j < 8; j++)
                    acc[i][j] = fmaf(a[i], w[j], acc[i][j]);
        }
        __syncthreads();
    }
#pragma unroll
    for (int i = 0; i < 4; i++) {
        int row = bm + ty + 16 * i;
#pragma unroll
        for (int j = 0; j < 8; j++) {
            int col = tx + 16 * j;
            if (col < AA)
                C[(size_t)row * LDF + col] = acc[i][j] + bias[col];
        }
    }
}

// ---------------- generic GEMM: C = A @ W^T + bias (opt relu) ------------
// BM=64, BN=128 (single N tile, N<=128), BK=32
__global__ void gemm64(const float* __restrict__ A, int lda,
                       const float* __restrict__ W, int ldw,
                       const float* __restrict__ bias,
                       float* __restrict__ C, int ldc,
                       int N, int K, int relu)
{
    __shared__ float As[32][65];
    __shared__ float Ws[32][129];
    int bm = blockIdx.x * 64;
    int tx = threadIdx.x & 15, ty = threadIdx.x >> 4;
    int tid = threadIdx.x;
    float acc[4][8] = {};
    for (int k0 = 0; k0 < K; k0 += 32) {
#pragma unroll
        for (int e = tid; e < 64 * 32; e += 256) {
            int m = e >> 5, kk = e & 31;
            As[kk][m] = (k0 + kk < K) ? A[(size_t)(bm + m) * lda + k0 + kk] : 0.f;
        }
#pragma unroll
        for (int e = tid; e < 128 * 32; e += 256) {
            int n = e >> 5, kk = e & 31;
            Ws[kk][n] = (n < N && k0 + kk < K) ? W[(size_t)n * ldw + k0 + kk] : 0.f;
        }
        __syncthreads();
#pragma unroll
        for (int kk = 0; kk < 32; kk++) {
            float a[4], w[8];
#pragma unroll
            for (int i = 0; i < 4; i++) a[i] = As[kk][ty + 16 * i];
#pragma unroll
            for (int j = 0; j < 8; j++) w[j] = Ws[kk][tx + 16 * j];
#pragma unroll
            for (int i = 0; i < 4; i++)
#pragma unroll
                for (int j = 0; j < 8; j++)
                    acc[i][j] = fmaf(a[i], w[j], acc[i][j]);
        }
        __syncthreads();
    }
#pragma unroll
    for (int i = 0; i < 4; i++) {
        int row = bm + ty + 16 * i;
#pragma unroll
        for (int j = 0; j < 8; j++) {
            int col = tx + 16 * j;
            if (col < N) {
                float v = acc[i][j] + (bias ? bias[col] : 0.f);
                if (relu) v = fmaxf(v, 0.f);
                C[(size_t)row * ldc + col] = v;
            }
        }
    }
}

// ---------------- fused attention -> P1, Pc ------------------------------
// block per (itile16, b); 512 threads = 16 warps (warp w owns row w);
// heads processed in 4 phases; P1/Pc accumulated in smem.
__global__ void attn_kernel(const float* __restrict__ q,
                            const float* __restrict__ k,
                            const float* __restrict__ syn,
                            const int* __restrict__ src_mask,
                            const float* __restrict__ pre,
                            float* __restrict__ P1, float* __restrict__ Pc)
{
    extern __shared__ float sm[];
    float* p1 = sm;                  // 16*512
    float* pc = p1 + 16 * LL;        // 16*512
    float* kh = pc + 16 * LL;        // 512*25
    float* qs = kh + LL * DKk;       // 16*100
    float* mk = qs + 16 * AA;        // 512
    int itile = blockIdx.x, b = blockIdx.y;
    int tid = threadIdx.x;
    int warp = tid >> 5, lane = tid & 31;

    for (int e = tid; e < 16 * LL; e += 512) { p1[e] = 0.f; pc[e] = 0.f; }
    for (int e = tid; e < 16 * AA; e += 512)
        qs[e] = q[(size_t)(b * LL + itile * 16 + e / AA) * AA + e % AA];
    mk[tid] = src_mask[b * LL + tid] ? 1.f : 0.f;

    float c0 = pre[0], c1 = pre[1], c2 = pre[2], c3 = pre[3];
    int i = warp;   // row within tile

    for (int h = 0; h < HH; h++) {
        __syncthreads();
        for (int e = tid; e < LL * DKk; e += 512) {
            int j = e / DKk, d = e % DKk;
            kh[e] = k[(size_t)(b * LL + j) * AA + h * DKk + d];
        }
        __syncthreads();
        const float* qrow = qs + i * AA + h * DKk;
        const float* synp = syn + ((size_t)((b * HH + h) * LL) + itile * 16 + i) * LL;
        float vals[16];
        float m = -1e30f;
#pragma unroll
        for (int t = 0; t < 16; t++) {
            int j = lane + 32 * t;
            const float* kr = kh + j * DKk;
            float dot = 0.f;
#pragma unroll
            for (int d = 0; d < DKk; d++) dot = fmaf(qrow[d], kr[d], dot);
            float s = (mk[j] != 0.f) ? dot * 0.2f : -1e9f;
            s += synp[j];
            vals[t] = s;
            m = fmaxf(m, s);
        }
        for (int o = 16; o; o >>= 1) m = fmaxf(m, __shfl_xor_sync(0xffffffffu, m, o));
        float sum = 0.f;
#pragma unroll
        for (int t = 0; t < 16; t++) { vals[t] = __expf(vals[t] - m); sum += vals[t]; }
        for (int o = 16; o; o >>= 1) sum += __shfl_xor_sync(0xffffffffu, sum, o);
        float invs = 1.f / sum;
        float ch = (h == 0) ? c0 : (h == 1) ? c1 : (h == 2) ? c2 : c3;
#pragma unroll
        for (int t = 0; t < 16; t++) {
            int j = lane + 32 * t;
            float a = vals[t] * invs;
            p1[i * LL + j] += a;
            pc[i * LL + j] += ch * a;
        }
    }
    __syncthreads();
    for (int e = tid; e < 16 * LL; e += 512) {
        int i2 = e >> 9, j = e & (LL - 1);
        size_t off = ((size_t)(b * LL) + itile * 16 + i2) * LL + j;
        P1[off] = p1[e];
        Pc[off] = pc[e];
    }
}

// ---------------- Ax = 0.25 * (P @ X  [+ corr + (V+Cb)*S]) ---------------
// P: [L x L] per b, X: [L x ldx] (first 100 cols), out: [L x 100] per b
__global__ void ax_kernel(const float* __restrict__ P,
                          const float* __restrict__ X, int ldx,
                          float* __restrict__ out, int mode,
                          const float* __restrict__ V,
                          const float* __restrict__ corrS,
                          const float* __restrict__ pre)
{
    __shared__ float Ps[32][65];
    __shared__ float Xs[32][129];
    int bi = blockIdx.x * 64, b = blockIdx.y;
    int tx = threadIdx.x & 15, ty = threadIdx.x >> 4;
    int tid = threadIdx.x;
    const float* Pb = P + (size_t)b * LL * LL;
    const float* Xb = X + (size_t)b * LL * ldx;
    float acc[4][8] = {};
    for (int k0 = 0; k0 < LL; k0 += 32) {
#pragma unroll
        for (int e = tid; e < 64 * 32; e += 256) {
            int m = e >> 5, kk = e & 31;
            Ps[kk][m] = Pb[(size_t)(bi + m) * LL + k0 + kk];
        }
        // X tile: 32 rows x 128 cols
#pragma unroll
        for (int e = tid; e < 32 * 128; e += 256) {
            int kk = e >> 7, d = e & 127;
            Xs[kk][d] = (d < AA) ? Xb[(size_t)(k0 + kk) * ldx + d] : 0.f;
        }
        __syncthreads();
#pragma unroll
        for (int kk = 0; kk < 32; kk++) {
            float a[4], x[8];
#pragma unroll
            for (int i = 0; i < 4; i++) a[i] = Ps[kk][ty + 16 * i];
#pragma unroll
            for (int j = 0; j < 8; j++) x[j] = Xs[kk][tx + 16 * j];
#pragma unroll
            for (int i = 0; i < 4; i++)
#pragma unroll
                for (int j = 0; j < 8; j++)
                    acc[i][j] = fmaf(a[i], x[j], acc[i][j]);
        }
        __syncthreads();
    }
    float Cb = mode ? pre[204] : 0.f;
#pragma unroll
    for (int i = 0; i < 4; i++) {
        int row = bi + ty + 16 * i;
        float vr = mode ? (V[b * LL + row] + Cb) : 0.f;
#pragma unroll
        for (int j = 0; j < 8; j++) {
            int col = tx + 16 * j;
            if (col < AA) {
                float r = acc[i][j];
                if (mode)
                    r += corrS[b * 2 * AA + col] + vr * corrS[b * 2 * AA + AA + col];
                out[((size_t)b * LL + row) * AA + col] = r * 0.25f;
            }
        }
    }
}

// ---------------- U, V per row (warp per row) ----------------
__global__ void uv_kernel(const float* __restrict__ x1,
                          const float* __restrict__ pre,
                          float* __restrict__ U, float* __restrict__ V)
{
    __shared__ float b1s[AA], b2s[AA];
    int tid = threadIdx.x;
    for (int e = tid; e < AA; e += 256) { b1s[e] = pre[4 + e]; b2s[e] = pre[104 + e]; }
    __syncthreads();
    int row = blockIdx.x * 8 + (tid >> 5);
    int lane = tid & 31;
    const float* xr = x1 + (size_t)row * LDF;
    float u = 0.f, v = 0.f;
    for (int d = lane; d < AA; d += 32) {
        float xv = xr[d];
        u = fmaf(xv, b1s[d], u);
        v = fmaf(xv, b2s[d], v);
    }
    for (int o = 16; o; o >>= 1) {
        u += __shfl_xor_sync(0xffffffffu, u, o);
        v += __shfl_xor_sync(0xffffffffu, v, o);
    }
    if (lane == 0) { U[row] = u; V[row] = v; }
}

// ---------------- corr[b][d] = sum_j U[j] x1[j,d]; S[b][d] = sum_j x1[j,d] -----
__global__ void corrS_kernel(const float* __restrict__ x1,
                             const float* __restrict__ U,
                             float* __restrict__ corrS)
{
    __shared__ float sc[2][128], ss[2][128];
    int b = blockIdx.x, tid = threadIdx.x;
    int d = tid & 127, half = tid >> 7;
    float c = 0.f, s = 0.f;
    if (d < AA) {
        for (int j = half; j < LL; j += 2) {
            float xv = x1[((size_t)b * LL + j) * LDF + d];
            c = fmaf(U[b * LL + j], xv, c);
            s += xv;
        }
    }
    sc[half][d] = c; ss[half][d] = s;
    __syncthreads();
    if (half == 0 && d < AA) {
        corrS[b * 2 * AA + d]      = sc[0][d] + sc[1][d];
        corrS[b * 2 * AA + AA + d] = ss[0][d] + ss[1][d];
    }
}

// ---------------- agg GEMM + relu + fused masked-mean pool ---------------
// node never materialized; column sums atomically accumulated into pool.
__global__ void gemm_agg(const float* __restrict__ A,       // feats, ld 300
                         const float* __restrict__ W,       // agg_w, 100 x 300
                         const float* __restrict__ bias,
                         float* __restrict__ pool)          // B x 100 raw sums
{
    __shared__ float As[32][65];
    __shared__ float Ws[32][129];
    __shared__ float red[16][129];
    int bm = blockIdx.x * 64;
    int b = bm >> 9;                 // 512 rows per batch, 64 | 512
    int tx = threadIdx.x & 15, ty = threadIdx.x >> 4;
    int tid = threadIdx.x;
    float acc[4][8] = {};
    for (int k0 = 0; k0 < LDF; k0 += 32) {
#pragma unroll
        for (int e = tid; e < 64 * 32; e += 256) {
            int m = e >> 5, kk = e & 31;
            As[kk][m] = (k0 + kk < LDF) ? A[(size_t)(bm + m) * LDF + k0 + kk] : 0.f;
        }
#pragma unroll
        for (int e = tid; e < 128 * 32; e += 256) {
            int n = e >> 5, kk = e & 31;
            Ws[kk][n] = (n < AA && k0 + kk < LDF) ? W[(size_t)n * LDF + k0 + kk] : 0.f;
        }
        __syncthreads();
#pragma unroll
        for (int kk = 0; kk < 32; kk++) {
            float a[4], w[8];
#pragma unroll
            for (int i = 0; i < 4; i++) a[i] = As[kk][ty + 16 * i];
#pragma unroll
            for (int j = 0; j < 8; j++) w[j] = Ws[kk][tx + 16 * j];
#pragma unroll
            for (int i = 0; i < 4; i++)
#pragma unroll
                for (int j = 0; j < 8; j++)
                    acc[i][j] = fmaf(a[i], w[j], acc[i][j]);
        }
        __syncthreads();
    }
    // relu + per-block column sums
#pragma unroll
    for (int j = 0; j < 8; j++) {
        int col = tx + 16 * j;
        float p = 0.f;
#pragma unroll
        for (int i = 0; i < 4; i++) {
            float v = acc[i][j] + (col < AA ? bias[col] : 0.f);
            p += fmaxf(v, 0.f);
        }
        red[ty][col] = p;
    }
    __syncthreads();
    if (ty == 0) {
#pragma unroll
        for (int j = 0; j < 8; j++) {
            int col = tx + 16 * j;
            if (col < AA) {
                float s = 0.f;
#pragma unroll
                for (int t = 0; t < 16; t++) s += red[t][col];
                atomicAdd(&pool[b * AA + col], s);
            }
        }
    }
}

// ---------------- logits: mask lens + pooled / len @ cls ----------------
__global__ void logits_kernel(const float* __restrict__ pool,
                              const int* __restrict__ mask_ids,
                              const float* __restrict__ cls_w,
                              const float* __restrict__ cls_b,
                              float* __restrict__ out)
{
    __shared__ float linv[BB];
    __shared__ float pr[BB * AA];
    __shared__ float cw[PP * AA];
    int tid = threadIdx.x;              // 512
    int warp = tid >> 5, lane = tid & 31;
    if (warp < BB) {
        int ms = 0;
#pragma unroll
        for (int t = 0; t < 16; t++) ms += mask_ids[warp * LL + lane + 32 * t];
        for (int o = 16; o; o >>= 1) ms += __shfl_xor_sync(0xffffffffu, ms, o);
        if (lane == 0) linv[warp] = 1.f / fmaxf((float)ms, 1.f);
    }
    for (int e = tid; e < BB * AA; e += 512) pr[e] = pool[e];
    for (int e = tid; e < PP * AA; e += 512) cw[e] = cls_w[e];
    __syncthreads();
    if (tid < BB * PP) {
        int b = tid / PP, p = tid % PP;
        float s0 = 0.f, s1 = 0.f, s2 = 0.f, s3 = 0.f;
#pragma unroll
        for (int d = 0; d < AA; d += 4) {
            s0 = fmaf(pr[b * AA + d + 0], cw[p * AA + d + 0], s0);
            s1 = fmaf(pr[b * AA + d + 1], cw[p * AA + d + 1], s1);
            s2 = fmaf(pr[b * AA + d + 2], cw[p * AA + d + 2], s2);
            s3 = fmaf(pr[b * AA + d + 3], cw[p * AA + d + 3], s3);
        }
        out[tid] = cls_b[p] + linv[b] * (s0 + s1 + s2 + s3);
    }
}

// ---------------- launch ----------------
extern "C" void kernel_launch(void* const* d_in, const int* in_sizes, int n_in,
                              void* d_out, int out_size)
{
    const float* seq      = (const float*)d_in[0];
    const float* syn      = (const float*)d_in[1];
    const float* ln_a     = (const float*)d_in[2];
    const float* ln_b     = (const float*)d_in[3];
    const float* Wxx_w    = (const float*)d_in[4];
    const float* Wxx_b    = (const float*)d_in[5];
    const float* q_w      = (const float*)d_in[6];
    const float* q_b      = (const float*)d_in[7];
    const float* k_w      = (const float*)d_in[8];
    const float* k_b      = (const float*)d_in[9];
    const float* W_w      = (const float*)d_in[10];
    const float* W_b      = (const float*)d_in[11];
    const float* Wx_w     = (const float*)d_in[12];
    const float* Wx_b     = (const float*)d_in[13];
    const float* agg_w    = (const float*)d_in[14];
    const float* agg_b    = (const float*)d_in[15];
    const float* cls_w    = (const float*)d_in[16];
    const float* cls_b    = (const float*)d_in[17];
    const int*   mask_ids = (const int*)d_in[18];
    const int*   src_mask = (const int*)d_in[19];
    float* out = (float*)d_out;

    float *feats, *q, *k, *P1, *Pc, *Ax, *U, *V, *corrS, *pre, *pool, *mean, *inv;
    cudaGetSymbolAddress((void**)&feats, g_feats);
    cudaGetSymbolAddress((void**)&q,     g_q);
    cudaGetSymbolAddress((void**)&k,     g_k);
    cudaGetSymbolAddress((void**)&P1,    g_P1);
    cudaGetSymbolAddress((void**)&Pc,    g_Pc);
    cudaGetSymbolAddress((void**)&Ax,    g_Ax);
    cudaGetSymbolAddress((void**)&U,     g_U);
    cudaGetSymbolAddress((void**)&V,     g_V);
    cudaGetSymbolAddress((void**)&corrS, g_corrS);
    cudaGetSymbolAddress((void**)&pre,   g_pre);
    cudaGetSymbolAddress((void**)&pool,  g_pool);
    cudaGetSymbolAddress((void**)&mean,  g_mean);
    cudaGetSymbolAddress((void**)&inv,   g_inv);

    const int M = BB * LL;           // 8192
    const int GM = M / 64;           // 128 blocks

    // 0) precompute folded weights + zero pool
    precomp_kernel<<<1, 256>>>(Wx_w, Wx_b, pre, pool);
    // 1) LN stats
    ln_stats<<<M / 8, 256>>>(seq, mean, inv);
    // 2) x = LN(seq) @ Wxx^T + b  (LN fused)
    gemm_ln<<<GM, 256>>>(seq, ln_a, ln_b, mean, inv, Wxx_w, Wxx_b, feats);
    // 3) q, k
    gemm64<<<GM, 256>>>(feats, LDF, q_w, AA, q_b, q, AA, AA, AA, 0);
    gemm64<<<GM, 256>>>(feats, LDF, k_w, AA, k_b, k, AA, AA, AA, 0);
    // 4) attention -> P1 (sum_h), Pc (sum_h c_h)
    const int ATTN_SMEM = (2 * 16 * LL + LL * DKk + 16 * AA + LL) * (int)sizeof(float);
    cudaFuncSetAttribute(attn_kernel, cudaFuncAttributeMaxDynamicSharedMemorySize, ATTN_SMEM);
    attn_kernel<<<dim3(LL / 16, BB), 512, ATTN_SMEM>>>(q, k, syn, src_mask, pre, P1, Pc);
    // 5) layer 1: Ax1 = 0.25 * P1 @ x ;  x1 = relu(Ax1 @ W^T + b)
    ax_kernel<<<dim3(LL / 64, BB), 256>>>(P1, feats, LDF, Ax, 0, nullptr, nullptr, nullptr);
    gemm64<<<GM, 256>>>(Ax, AA, W_w, AA, W_b, feats + AA, LDF, AA, AA, 1);
    // 6) rank-1 corrections from x1
    uv_kernel<<<M / 8, 256>>>(feats + AA, pre, U, V);
    corrS_kernel<<<BB, 256>>>(feats + AA, U, corrS);
    // 7) layer 2: Ax2 = 0.25*(Pc @ x1 + corr + (V+Cb)*S);  x2 = relu(Ax2 @ W^T + b)
    ax_kernel<<<dim3(LL / 64, BB), 256>>>(Pc, feats + AA, LDF, Ax, 1, V, corrS, pre);
    gemm64<<<GM, 256>>>(Ax, AA, W_w, AA, W_b, feats + 2 * AA, LDF, AA, AA, 1);
    // 8) aggregate + relu + masked mean pool (node never materialized)
    gemm_agg<<<GM, 256>>>(feats, agg_w, agg_b, pool);
    // 9) logits
    logits_kernel<<<1, 512>>>(pool, mask_ids, cls_w, cls_b, out);
}

// round 6
// speedup vs baseline: 1.7258x; 1.1040x over previous
#include <cuda_runtime.h>
#include <math.h>

constexpr int BB = 16, LL = 512, DD = 768, HH = 4, AA = 100, DKk = 25, PP = 3;
constexpr int LDF = 3 * AA;            // 300
constexpr int LDW_X = HH + 2 * AA;     // 204
constexpr float EPSf = 1e-6f;

// ---------------- device scratch ----------------
__device__ float g_feats [BB * LL * LDF];       // x | x1 | x2
__device__ float g_q     [BB * LL * AA];
__device__ float g_k     [BB * LL * AA];
__device__ float g_P1    [BB * LL * LL];        // sum_h adj_h          (16 MB)
__device__ float g_Pc    [BB * LL * LL];        // sum_h c_h adj_h      (16 MB)
__device__ float g_U     [BB * LL];
__device__ float g_V     [BB * LL];
__device__ float g_corrS [BB * 2 * AA];         // per b: corr[100], S[100]
__device__ float g_pre   [256];                 // c[4], b1s[100], b2s[100], Cb
__device__ float g_pool  [BB * AA];             // pooled raw sums
__device__ float g_mean  [BB * LL];
__device__ float g_inv   [BB * LL];

// ---------------- precompute: c, b1s, b2s, Cb + zero pool ----------------
__global__ void precomp_kernel(const float* __restrict__ Wxw,
                               const float* __restrict__ Wxb,
                               float* __restrict__ pre, float* __restrict__ pool)
{
    int t = threadIdx.x;
    if (t < 4) {
        float s = 0.f;
        for (int g = 0; g < HH; g++) s += Wxw[g * LDW_X + t];
        pre[t] = s;
    } else if (t < 104) {
        int d = t - 4; float s = 0.f;
        for (int g = 0; g < HH; g++) s += Wxw[g * LDW_X + HH + d];
        pre[t] = s;
    } else if (t < 204) {
        int d = t - 104; float s = 0.f;
        for (int g = 0; g < HH; g++) s += Wxw[g * LDW_X + HH + AA + d];
        pre[t] = s;
    } else if (t == 204) {
        pre[204] = Wxb[0] + Wxb[1] + Wxb[2] + Wxb[3];
    }
    for (int e = t; e < BB * AA; e += 256) pool[e] = 0.f;
}

// ---------------- LN stats (one warp per row) ----------------
__global__ void ln_stats(const float* __restrict__ x,
                         float* __restrict__ mean, float* __restrict__ inv)
{
    int row = blockIdx.x * 8 + (threadIdx.x >> 5);
    int lane = threadIdx.x & 31;
    const float* xr = x + (size_t)row * DD;
    float s = 0.f, s2 = 0.f;
    for (int d = lane; d < DD; d += 32) { float v = xr[d]; s += v; s2 = fmaf(v, v, s2); }
    for (int o = 16; o; o >>= 1) {
        s  += __shfl_xor_sync(0xffffffffu, s,  o);
        s2 += __shfl_xor_sync(0xffffffffu, s2, o);
    }
    if (lane == 0) {
        float m   = s / (float)DD;
        float var = (s2 - (float)DD * m * m) / (float)(DD - 1);
        mean[row] = m;
        inv[row]  = 1.f / (sqrtf(fmaxf(var, 0.f)) + EPSf);
    }
}

// ---------------- Wxx GEMM with fused LayerNorm (K=768, compute-bound) ----
__global__ void gemm_ln(const float* __restrict__ seq,
                        const float* __restrict__ ga, const float* __restrict__ gb,
                        const float* __restrict__ mean, const float* __restrict__ inv,
                        const float* __restrict__ W, const float* __restrict__ bias,
                        float* __restrict__ C)
{
    __shared__ float As[32][65];
    __shared__ float Ws[32][129];
    __shared__ float rmean[64], rinv[64];
    int bm = blockIdx.x * 64;
    int tx = threadIdx.x & 15, ty = threadIdx.x >> 4;
    int tid = threadIdx.x;
    if (tid < 64) { rmean[tid] = mean[bm + tid]; rinv[tid] = inv[bm + tid]; }
    __syncthreads();
    float acc[4][8] = {};
    for (int k0 = 0; k0 < DD; k0 += 32) {
#pragma unroll
        for (int e = tid; e < 64 * 32; e += 256) {
            int m = e >> 5, kk = e & 31;
            int kc = k0 + kk;
            float v = seq[(size_t)(bm + m) * DD + kc];
            As[kk][m] = fmaf(__ldg(&ga[kc]), (v - rmean[m]) * rinv[m], __ldg(&gb[kc]));
        }
#pragma unroll
        for (int e = tid; e < 128 * 32; e += 256) {
            int n = e >> 5, kk = e & 31;
            Ws[kk][n] = (n < AA) ? W[(size_t)n * DD + k0 + kk] : 0.f;
        }
        __syncthreads();
#pragma unroll
        for (int kk = 0; kk < 32; kk++) {
            float a[4], w[8];
#pragma unroll
            for (int i = 0; i < 4; i++) a[i] = As[kk][ty + 16 * i];
#pragma unroll
            for (int j = 0; j < 8; j++) w[j] = Ws[kk][tx + 16 * j];
#pragma unroll
            for (int i = 0; i < 4; i++)
#pragma unroll
                for (int j = 0; j < 8; j++)
                    acc[i][j] = fmaf(a[i], w[j], acc[i][j]);
        }
        __syncthreads();
    }
#pragma unroll
    for (int i = 0; i < 4; i++) {
        int row = bm + ty + 16 * i;
#pragma unroll
        for (int j = 0; j < 8; j++) {
            int col = tx + 16 * j;
            if (col < AA)
                C[(size_t)row * LDF + col] = acc[i][j] + bias[col];
        }
    }
}

// ---------------- fused q+k GEMM: whole K=100 in smem, no K-loop stalls ----
__global__ void qk_kernel(const float* __restrict__ A,
                          const float* __restrict__ qw, const float* __restrict__ qb,
                          const float* __restrict__ kw, const float* __restrict__ kb,
                          float* __restrict__ qo, float* __restrict__ ko)
{
    extern __shared__ float sm[];
    float* As = sm;                 // 64*101
    float* Wq = As + 64 * 101;      // 100*129
    float* Wk = Wq + 100 * 129;     // 100*129
    int bm = blockIdx.x * 64;
    int tid = threadIdx.x;
    int tx = tid & 15, ty = tid >> 4;
    for (int e = tid; e < 64 * AA; e += 256) {
        int r = e / AA, c = e % AA;
        As[r * 101 + c] = A[(size_t)(bm + r) * LDF + c];
    }
    for (int e = tid; e < AA * AA; e += 256) {
        int n = e / AA, kk = e % AA;
        Wq[kk * 129 + n] = qw[e];
        Wk[kk * 129 + n] = kw[e];
    }
    __syncthreads();
    float aq[4][8] = {}, ak[4][8] = {};
#pragma unroll 4
    for (int kk = 0; kk < AA; kk++) {
        float a[4], wq[8], wk[8];
#pragma unroll
        for (int i = 0; i < 4; i++) a[i] = As[(ty + 16 * i) * 101 + kk];
#pragma unroll
        for (int j = 0; j < 8; j++) {
            wq[j] = Wq[kk * 129 + tx + 16 * j];
            wk[j] = Wk[kk * 129 + tx + 16 * j];
        }
#pragma unroll
        for (int i = 0; i < 4; i++)
#pragma unroll
            for (int j = 0; j < 8; j++) {
                aq[i][j] = fmaf(a[i], wq[j], aq[i][j]);
                ak[i][j] = fmaf(a[i], wk[j], ak[i][j]);
            }
    }
#pragma unroll
    for (int i = 0; i < 4; i++) {
        int row = bm + ty + 16 * i;
#pragma unroll
        for (int j = 0; j < 8; j++) {
            int col = tx + 16 * j;
            if (col < AA) {
                qo[(size_t)row * AA + col] = aq[i][j] + qb[col];
                ko[(size_t)row * AA + col] = ak[i][j] + kb[col];
            }
        }
    }
}

// ---------------- attention v2: 4x4 micro-tiles, reg-resident P1/Pc -------
// block (itile16, b), 512 threads: tx = tid&127 (j base), ag = tid>>7.
// thread covers rows {ag,ag+4,ag+8,ag+12}, cols {tx, tx+128, tx+256, tx+384}.
__global__ void attn2_kernel(const float* __restrict__ q,
                             const float* __restrict__ k,
                             const float* __restrict__ syn,
                             const int* __restrict__ src_mask,
                             const float* __restrict__ pre,
                             float* __restrict__ P1, float* __restrict__ Pc)
{
    extern __shared__ float sm[];
    float* kh   = sm;                     // 512*25
    float* qs   = kh + LL * DKk;          // 16*100
    float* mkf  = qs + 16 * AA;           // 512
    float* redm = mkf + LL;               // 16*4
    float* reds = redm + 64;              // 16*4
    int itile = blockIdx.x, b = blockIdx.y;
    int tid = threadIdx.x;
    int tx = tid & 127, ag = tid >> 7;
    int wg = (tid >> 5) & 3;
    int row0 = itile * 16;

    for (int e = tid; e < 16 * AA; e += 512)
        qs[e] = q[(size_t)(b * LL + row0 + e / AA) * AA + e % AA];
    mkf[tid] = src_mask[b * LL + tid] ? 1.f : 0.f;
    float ch[4] = {__ldg(pre), __ldg(pre + 1), __ldg(pre + 2), __ldg(pre + 3)};
    float p1a[4][4] = {}, pca[4][4] = {};

    for (int h = 0; h < HH; h++) {
        __syncthreads();
        for (int e = tid; e < LL * DKk; e += 512) {
            int j = e / DKk, d = e % DKk;
            kh[e] = k[(size_t)(b * LL + j) * AA + h * DKk + d];
        }
        __syncthreads();
        float s[4][4] = {};
#pragma unroll
        for (int d = 0; d < DKk; d++) {
            float qv[4], kv[4];
#pragma unroll
            for (int ii = 0; ii < 4; ii++) qv[ii] = qs[(ag + 4 * ii) * AA + h * DKk + d];
#pragma unroll
            for (int jj = 0; jj < 4; jj++) kv[jj] = kh[(tx + 128 * jj) * DKk + d];
#pragma unroll
            for (int ii = 0; ii < 4; ii++)
#pragma unroll
                for (int jj = 0; jj < 4; jj++)
                    s[ii][jj] = fmaf(qv[ii], kv[jj], s[ii][jj]);
        }
        const float* synb = syn + ((size_t)(b * HH + h) * LL + row0) * LL;
        float mloc[4];
#pragma unroll
        for (int ii = 0; ii < 4; ii++) {
            mloc[ii] = -1e30f;
#pragma unroll
            for (int jj = 0; jj < 4; jj++) {
                int j = tx + 128 * jj;
                float v = (mkf[j] != 0.f) ? s[ii][jj] * 0.2f : -1e9f;
                v += synb[(size_t)(ag + 4 * ii) * LL + j];
                s[ii][jj] = v;
                mloc[ii] = fmaxf(mloc[ii], v);
            }
        }
        for (int o = 16; o; o >>= 1)
#pragma unroll
            for (int ii = 0; ii < 4; ii++)
                mloc[ii] = fmaxf(mloc[ii], __shfl_xor_sync(0xffffffffu, mloc[ii], o));
        if ((tid & 31) == 0)
#pragma unroll
            for (int ii = 0; ii < 4; ii++)
                redm[(ag + 4 * ii) * 4 + wg] = mloc[ii];
        __syncthreads();
        float m[4], ssum[4];
#pragma unroll
        for (int ii = 0; ii < 4; ii++) {
            int r = ag + 4 * ii;
            m[ii] = fmaxf(fmaxf(redm[r * 4], redm[r * 4 + 1]),
                          fmaxf(redm[r * 4 + 2], redm[r * 4 + 3]));
            ssum[ii] = 0.f;
#pragma unroll
            for (int jj = 0; jj < 4; jj++) {
                float e = __expf(s[ii][jj] - m[ii]);
                s[ii][jj] = e;
                ssum[ii] += e;
            }
        }
        for (int o = 16; o; o >>= 1)
#pragma unroll
            for (int ii = 0; ii < 4; ii++)
                ssum[ii] += __shfl_xor_sync(0xffffffffu, ssum[ii], o);
        if ((tid & 31) == 0)
#pragma unroll
            for (int ii = 0; ii < 4; ii++)
                reds[(ag + 4 * ii) * 4 + wg] = ssum[ii];
        __syncthreads();
#pragma unroll
        for (int ii = 0; ii < 4; ii++) {
            int r = ag + 4 * ii;
            float inv = 1.f / (reds[r * 4] + reds[r * 4 + 1] + reds[r * 4 + 2] + reds[r * 4 + 3]);
#pragma unroll
            for (int jj = 0; jj < 4; jj++) {
                float a = s[ii][jj] * inv;
                p1a[ii][jj] += a;
                pca[ii][jj] += ch[h] * a;
            }
        }
    }
#pragma unroll
    for (int ii = 0; ii < 4; ii++) {
        size_t off = ((size_t)(b * LL) + row0 + ag + 4 * ii) * LL + tx;
#pragma unroll
        for (int jj = 0; jj < 4; jj++) {
            P1[off + 128 * jj] = p1a[ii][jj];
            Pc[off + 128 * jj] = pca[ii][jj];
        }
    }
}

// ---------------- fused GCN layer: 0.25*(P@X [+corr]) -> @W^T -> relu -----
__global__ void layer_kernel(const float* __restrict__ P,
                             const float* __restrict__ Xin,       // ld LDF
                             const float* __restrict__ Ww,
                             const float* __restrict__ Wb,
                             float* __restrict__ Xout,            // ld LDF
                             int mode,
                             const float* __restrict__ V,
                             const float* __restrict__ corrS,
                             const float* __restrict__ pre)
{
    extern __shared__ float sm[];
    float* Axs  = sm;                    // 64*101
    float* reg0 = Axs + 64 * 101;        // max( Ps 32*65 + Xs 32*129 , Ws 100*129 )
    float* Ps = reg0;                    // 32*65
    float* Xs = reg0 + 32 * 65;          // 32*129
    float* Ws = reg0;                    // phase 2 alias
    int bi = blockIdx.x * 64, b = blockIdx.y;
    int tid = threadIdx.x;
    int tx = tid & 15, ty = tid >> 4;
    const float* Pb = P + (size_t)b * LL * LL;
    const float* Xb = Xin + (size_t)b * LL * LDF;
    float acc[4][8] = {};
    for (int k0 = 0; k0 < LL; k0 += 32) {
#pragma unroll
        for (int e = tid; e < 64 * 32; e += 256) {
            int m = e >> 5, kk = e & 31;
            Ps[kk * 65 + m] = Pb[(size_t)(bi + m) * LL + k0 + kk];
        }
#pragma unroll
        for (int e = tid; e < 32 * 128; e += 256) {
            int kk = e >> 7, d = e & 127;
            Xs[kk * 129 + d] = (d < AA) ? Xb[(size_t)(k0 + kk) * LDF + d] : 0.f;
        }
        __syncthreads();
#pragma unroll
        for (int kk = 0; kk < 32; kk++) {
            float a[4], x[8];
#pragma unroll
            for (int i = 0; i < 4; i++) a[i] = Ps[kk * 65 + ty + 16 * i];
#pragma unroll
            for (int j = 0; j < 8; j++) x[j] = Xs[kk * 129 + tx + 16 * j];
#pragma unroll
            for (int i = 0; i < 4; i++)
#pragma unroll
                for (int j = 0; j < 8; j++)
                    acc[i][j] = fmaf(a[i], x[j], acc[i][j]);
        }
        __syncthreads();
    }
    // corrections + store Ax to smem
    float Cb = mode ? pre[204] : 0.f;
#pragma unroll
    for (int i = 0; i < 4; i++) {
        int row = ty + 16 * i;
        float vr = mode ? (V[b * LL + bi + row] + Cb) : 0.f;
#pragma unroll
        for (int j = 0; j < 8; j++) {
            int col = tx + 16 * j;
            if (col < AA) {
                float r = acc[i][j];
                if (mode)
                    r += corrS[b * 2 * AA + col] + vr * corrS[b * 2 * AA + AA + col];
                Axs[row * 101 + col] = r * 0.25f;
            }
        }
    }
    // phase 2: load full W (100x100), aliases Ps/Xs (safe after last sync above)
    for (int e = tid; e < AA * AA; e += 256) {
        int n = e / AA, kk = e % AA;
        Ws[kk * 129 + n] = Ww[e];
    }
    __syncthreads();
    float acc2[4][8] = {};
#pragma unroll 4
    for (int kk = 0; kk < AA; kk++) {
        float a[4], w[8];
#pragma unroll
        for (int i = 0; i < 4; i++) a[i] = Axs[(ty + 16 * i) * 101 + kk];
#pragma unroll
        for (int j = 0; j < 8; j++) w[j] = Ws[kk * 129 + tx + 16 * j];
#pragma unroll
        for (int i = 0; i < 4; i++)
#pragma unroll
            for (int j = 0; j < 8; j++)
                acc2[i][j] = fmaf(a[i], w[j], acc2[i][j]);
    }
#pragma unroll
    for (int i = 0; i < 4; i++) {
        size_t row = (size_t)b * LL + bi + ty + 16 * i;
#pragma unroll
        for (int j = 0; j < 8; j++) {
            int col = tx + 16 * j;
            if (col < AA)
                Xout[row * LDF + col] = fmaxf(acc2[i][j] + Wb[col], 0.f);
        }
    }
}

// ---------------- U, V per row (warp per row) ----------------
__global__ void uv_kernel(const float* __restrict__ x1,
                          const float* __restrict__ pre,
                          float* __restrict__ U, float* __restrict__ V)
{
    __shared__ float b1s[AA], b2s[AA];
    int tid = threadIdx.x;
    for (int e = tid; e < AA; e += 256) { b1s[e] = pre[4 + e]; b2s[e] = pre[104 + e]; }
    __syncthreads();
    int row = blockIdx.x * 8 + (tid >> 5);
    int lane = tid & 31;
    const float* xr = x1 + (size_t)row * LDF;
    float u = 0.f, v = 0.f;
    for (int d = lane; d < AA; d += 32) {
        float xv = xr[d];
        u = fmaf(xv, b1s[d], u);
        v = fmaf(xv, b2s[d], v);
    }
    for (int o = 16; o; o >>= 1) {
        u += __shfl_xor_sync(0xffffffffu, u, o);
        v += __shfl_xor_sync(0xffffffffu, v, o);
    }
    if (lane == 0) { U[row] = u; V[row] = v; }
}

// ---------------- corr / S ----------------
__global__ void corrS_kernel(const float* __restrict__ x1,
                             const float* __restrict__ U,
                             float* __restrict__ corrS)
{
    __shared__ float sc[2][128], ss[2][128];
    int b = blockIdx.x, tid = threadIdx.x;
    int d = tid & 127, half = tid >> 7;
    float c = 0.f, s = 0.f;
    if (d < AA) {
        for (int j = half; j < LL; j += 2) {
            float xv = x1[((size_t)b * LL + j) * LDF + d];
            c = fmaf(U[b * LL + j], xv, c);
            s += xv;
        }
    }
    sc[half][d] = c; ss[half][d] = s;
    __syncthreads();
    if (half == 0 && d < AA) {
        corrS[b * 2 * AA + d]      = sc[0][d] + sc[1][d];
        corrS[b * 2 * AA + AA + d] = ss[0][d] + ss[1][d];
    }
}

// ---------------- agg GEMM (full-A in smem) + relu + fused pool -----------
__global__ void gemm_agg(const float* __restrict__ A,       // feats, ld 300
                         const float* __restrict__ W,       // agg_w, 100 x 300
                         const float* __restrict__ bias,
                         float* __restrict__ pool)
{
    extern __shared__ float sm[];
    float* As  = sm;                  // 64*301
    float* Ws  = As + 64 * 301;       // 32*129
    float* red = Ws + 32 * 129;       // 16*129
    int bm = blockIdx.x * 64;
    int b = bm >> 9;
    int tid = threadIdx.x;
    int tx = tid & 15, ty = tid >> 4;
    for (int e = tid; e < 64 * LDF; e += 256) {
        int r = e / LDF, c = e % LDF;
        As[r * 301 + c] = A[(size_t)(bm + r) * LDF + c];
    }
    __syncthreads();
    float acc[4][8] = {};
    for (int k0 = 0; k0 < LDF; k0 += 32) {
        int kmax = LDF - k0 < 32 ? LDF - k0 : 32;
#pragma unroll
        for (int e = tid; e < 32 * AA; e += 256) {
            int n = e >> 5, kk = e & 31;
            Ws[kk * 129 + n] = (k0 + kk < LDF) ? W[(size_t)n * LDF + k0 + kk] : 0.f;
        }
        __syncthreads();
        for (int kk = 0; kk < kmax; kk++) {
            float a[4], w[8];
#pragma unroll
            for (int i = 0; i < 4; i++) a[i] = As[(ty + 16 * i) * 301 + k0 + kk];
#pragma unroll
            for (int j = 0; j < 8; j++) w[j] = (tx + 16 * j < AA) ? Ws[kk * 129 + tx + 16 * j] : 0.f;
#pragma unroll
            for (int i = 0; i < 4; i++)
#pragma unroll
                for (int j = 0; j < 8; j++)
                    acc[i][j] = fmaf(a[i], w[j], acc[i][j]);
        }
        __syncthreads();
    }
    // relu + per-block column sums -> atomic pool
#pragma unroll
    for (int j = 0; j < 8; j++) {
        int col = tx + 16 * j;
        float p = 0.f;
#pragma unroll
        for (int i = 0; i < 4; i++) {
            float v = acc[i][j] + (col < AA ? bias[col] : 0.f);
            p += fmaxf(v, 0.f);
        }
        red[ty * 129 + col] = p;
    }
    __syncthreads();
    if (ty == 0) {
#pragma unroll
        for (int j = 0; j < 8; j++) {
            int col = tx + 16 * j;
            if (col < AA) {
                float s = 0.f;
#pragma unroll
                for (int t = 0; t < 16; t++) s += red[t * 129 + col];
                atomicAdd(&pool[b * AA + col], s);
            }
        }
    }
}

// ---------------- logits ----------------
__global__ void logits_kernel(const float* __restrict__ pool,
                              const int* __restrict__ mask_ids,
                              const float* __restrict__ cls_w,
                              const float* __restrict__ cls_b,
                              float* __restrict__ out)
{
    __shared__ float linv[BB];
    __shared__ float pr[BB * AA];
    __shared__ float cw[PP * AA];
    int tid = threadIdx.x;              // 512
    int warp = tid >> 5, lane = tid & 31;
    if (warp < BB) {
        int ms = 0;
#pragma unroll
        for (int t = 0; t < 16; t++) ms += mask_ids[warp * LL + lane + 32 * t];
        for (int o = 16; o; o >>= 1) ms += __shfl_xor_sync(0xffffffffu, ms, o);
        if (lane == 0) linv[warp] = 1.f / fmaxf((float)ms, 1.f);
    }
    for (int e = tid; e < BB * AA; e += 512) pr[e] = pool[e];
    for (int e = tid; e < PP * AA; e += 512) cw[e] = cls_w[e];
    __syncthreads();
    if (tid < BB * PP) {
        int b = tid / PP, p = tid % PP;
        float s0 = 0.f, s1 = 0.f, s2 = 0.f, s3 = 0.f;
#pragma unroll
        for (int d = 0; d < AA; d += 4) {
            s0 = fmaf(pr[b * AA + d + 0], cw[p * AA + d + 0], s0);
            s1 = fmaf(pr[b * AA + d + 1], cw[p * AA + d + 1], s1);
            s2 = fmaf(pr[b * AA + d + 2], cw[p * AA + d + 2], s2);
            s3 = fmaf(pr[b * AA + d + 3], cw[p * AA + d + 3], s3);
        }
        out[tid] = cls_b[p] + linv[b] * (s0 + s1 + s2 + s3);
    }
}

// ---------------- launch ----------------
extern "C" void kernel_launch(void* const* d_in, const int* in_sizes, int n_in,
                              void* d_out, int out_size)
{
    const float* seq      = (const float*)d_in[0];
    const float* syn      = (const float*)d_in[1];
    const float* ln_a     = (const float*)d_in[2];
    const float* ln_b     = (const float*)d_in[3];
    const float* Wxx_w    = (const float*)d_in[4];
    const float* Wxx_b    = (const float*)d_in[5];
    const float* q_w      = (const float*)d_in[6];
    const float* q_b      = (const float*)d_in[7];
    const float* k_w      = (const float*)d_in[8];
    const float* k_b      = (const float*)d_in[9];
    const float* W_w      = (const float*)d_in[10];
    const float* W_b      = (const float*)d_in[11];
    const float* Wx_w     = (const float*)d_in[12];
    const float* Wx_b     = (const float*)d_in[13];
    const float* agg_w    = (const float*)d_in[14];
    const float* agg_b    = (const float*)d_in[15];
    const float* cls_w    = (const float*)d_in[16];
    const float* cls_b    = (const float*)d_in[17];
    const int*   mask_ids = (const int*)d_in[18];
    const int*   src_mask = (const int*)d_in[19];
    float* out = (float*)d_out;

    float *feats, *q, *k, *P1, *Pc, *U, *V, *corrS, *pre, *pool, *mean, *inv;
    cudaGetSymbolAddress((void**)&feats, g_feats);
    cudaGetSymbolAddress((void**)&q,     g_q);
    cudaGetSymbolAddress((void**)&k,     g_k);
    cudaGetSymbolAddress((void**)&P1,    g_P1);
    cudaGetSymbolAddress((void**)&Pc,    g_Pc);
    cudaGetSymbolAddress((void**)&U,     g_U);
    cudaGetSymbolAddress((void**)&V,     g_V);
    cudaGetSymbolAddress((void**)&corrS, g_corrS);
    cudaGetSymbolAddress((void**)&pre,   g_pre);
    cudaGetSymbolAddress((void**)&pool,  g_pool);
    cudaGetSymbolAddress((void**)&mean,  g_mean);
    cudaGetSymbolAddress((void**)&inv,   g_inv);

    const int M = BB * LL;           // 8192
    const int GM = M / 64;           // 128

    const int QK_SMEM    = (64 * 101 + 2 * 100 * 129) * 4;
    const int ATTN_SMEM  = (LL * DKk + 16 * AA + LL + 128) * 4;
    const int LAYER_SMEM = (64 * 101 + 100 * 129) * 4;
    const int AGG_SMEM   = (64 * 301 + 32 * 129 + 16 * 129) * 4;
    cudaFuncSetAttribute(qk_kernel,    cudaFuncAttributeMaxDynamicSharedMemorySize, QK_SMEM);
    cudaFuncSetAttribute(attn2_kernel, cudaFuncAttributeMaxDynamicSharedMemorySize, ATTN_SMEM);
    cudaFuncSetAttribute(layer_kernel, cudaFuncAttributeMaxDynamicSharedMemorySize, LAYER_SMEM);
    cudaFuncSetAttribute(gemm_agg,     cudaFuncAttributeMaxDynamicSharedMemorySize, AGG_SMEM);

    // 0) folded weights + zero pool
    precomp_kernel<<<1, 256>>>(Wx_w, Wx_b, pre, pool);
    // 1) LN stats
    ln_stats<<<M / 8, 256>>>(seq, mean, inv);
    // 2) x = LN(seq) @ Wxx^T + b
    gemm_ln<<<GM, 256>>>(seq, ln_a, ln_b, mean, inv, Wxx_w, Wxx_b, feats);
    // 3) q & k in one kernel
    qk_kernel<<<GM, 256, QK_SMEM>>>(feats, q_w, q_b, k_w, k_b, q, k);
    // 4) attention -> P1, Pc
    attn2_kernel<<<dim3(LL / 16, BB), 512, ATTN_SMEM>>>(q, k, syn, src_mask, pre, P1, Pc);
    // 5) layer 1 fused: x1 = relu((0.25*P1@x) @ W^T + b)
    layer_kernel<<<dim3(LL / 64, BB), 256, LAYER_SMEM>>>(P1, feats, W_w, W_b, feats + AA,
                                                         0, nullptr, nullptr, nullptr);
    // 6) rank-1 corrections from x1
    uv_kernel<<<M / 8, 256>>>(feats + AA, pre, U, V);
    corrS_kernel<<<BB, 256>>>(feats + AA, U, corrS);
    // 7) layer 2 fused: x2 = relu((0.25*(Pc@x1 + corr + (V+Cb)*S)) @ W^T + b)
    layer_kernel<<<dim3(LL / 64, BB), 256, LAYER_SMEM>>>(Pc, feats + AA, W_w, W_b, feats + 2 * AA,
                                                         1, V, corrS, pre);
    // 8) aggregate + relu + masked mean pool
    gemm_agg<<<GM, 256, AGG_SMEM>>>(feats, agg_w, agg_b, pool);
    // 9) logits
    logits_kernel<<<1, 512>>>(pool, mask_ids, cls_w, cls_b, out);
}

// round 7
// speedup vs baseline: 1.8112x; 1.0495x over previous
#include <cuda_runtime.h>
#include <math.h>

constexpr int BB = 16, LL = 512, DD = 768, HH = 4, AA = 100, DKk = 25, PP = 3;
constexpr int LDF = 3 * AA;            // 300
constexpr int LDW_X = HH + 2 * AA;     // 204
constexpr float EPSf = 1e-6f;

// ---------------- device scratch ----------------
__device__ float g_feats [BB * LL * LDF];       // x | x1 | x2
__device__ float g_q     [BB * LL * AA];
__device__ float g_k     [BB * LL * AA];
__device__ float g_P1    [BB * LL * LL];        // sum_h adj_h          (16 MB)
__device__ float g_Pc    [BB * LL * LL];        // sum_h c_h adj_h      (16 MB)
__device__ float g_U     [BB * LL];
__device__ float g_V     [BB * LL];
__device__ float g_corrS [BB * 2 * AA];         // per b: corr[100], S[100]
__device__ float g_pre   [256];                 // c[4], b1s[100], b2s[100], Cb
__device__ float g_pool  [BB * AA];
__device__ float g_mean  [BB * LL];
__device__ float g_inv   [BB * LL];

// ---------------- precompute: c, b1s, b2s, Cb + zero pool ----------------
__global__ void precomp_kernel(const float* __restrict__ Wxw,
                               const float* __restrict__ Wxb,
                               float* __restrict__ pre, float* __restrict__ pool)
{
    int t = threadIdx.x;
    if (t < 4) {
        float s = 0.f;
        for (int g = 0; g < HH; g++) s += Wxw[g * LDW_X + t];
        pre[t] = s;
    } else if (t < 104) {
        int d = t - 4; float s = 0.f;
        for (int g = 0; g < HH; g++) s += Wxw[g * LDW_X + HH + d];
        pre[t] = s;
    } else if (t < 204) {
        int d = t - 104; float s = 0.f;
        for (int g = 0; g < HH; g++) s += Wxw[g * LDW_X + HH + AA + d];
        pre[t] = s;
    } else if (t == 204) {
        pre[204] = Wxb[0] + Wxb[1] + Wxb[2] + Wxb[3];
    }
    for (int e = t; e < BB * AA; e += 256) pool[e] = 0.f;
}

// ---------------- LN stats (one warp per row, float4) ----------------
__global__ void ln_stats(const float* __restrict__ x,
                         float* __restrict__ mean, float* __restrict__ inv)
{
    int row = blockIdx.x * 8 + (threadIdx.x >> 5);
    int lane = threadIdx.x & 31;
    const float4* xr = (const float4*)(x + (size_t)row * DD);
    float s = 0.f, s2 = 0.f;
#pragma unroll
    for (int d = lane; d < DD / 4; d += 32) {
        float4 v = xr[d];
        s += v.x + v.y + v.z + v.w;
        s2 = fmaf(v.x, v.x, s2); s2 = fmaf(v.y, v.y, s2);
        s2 = fmaf(v.z, v.z, s2); s2 = fmaf(v.w, v.w, s2);
    }
    for (int o = 16; o; o >>= 1) {
        s  += __shfl_xor_sync(0xffffffffu, s,  o);
        s2 += __shfl_xor_sync(0xffffffffu, s2, o);
    }
    if (lane == 0) {
        float m   = s / (float)DD;
        float var = (s2 - (float)DD * m * m) / (float)(DD - 1);
        mean[row] = m;
        inv[row]  = 1.f / (sqrtf(fmaxf(var, 0.f)) + EPSf);
    }
}

// ---------------- Wxx GEMM + fused LN; 512 thr, double-buffered ----------
__global__ __launch_bounds__(512) void gemm_ln(
    const float* __restrict__ seq,
    const float* __restrict__ ga, const float* __restrict__ gb,
    const float* __restrict__ mean, const float* __restrict__ inv,
    const float* __restrict__ W, const float* __restrict__ bias,
    float* __restrict__ C)
{
    extern __shared__ float sm[];
    float* Asb[2] = { sm, sm + 2080 };                 // [kk][m] 32x65
    float* Wsb[2] = { sm + 4160, sm + 4160 + 4128 };   // [kk][n] 32x129
    __shared__ float rmean[64], rinv[64];
    int bm = blockIdx.x * 64;
    int tid = threadIdx.x, tx = tid & 15, ty = tid >> 4;   // ty 0..31
    if (tid < 64) { rmean[tid] = mean[bm + tid]; rinv[tid] = inv[bm + tid]; }
    __syncthreads();
    // stage tile 0
    for (int e = tid; e < 64 * 32; e += 512) {
        int m = e >> 5, kk = e & 31;
        float v = seq[(size_t)(bm + m) * DD + kk];
        Asb[0][kk * 65 + m] = fmaf(__ldg(&ga[kk]), (v - rmean[m]) * rinv[m], __ldg(&gb[kk]));
    }
    for (int e = tid; e < 128 * 32; e += 512) {
        int n = e >> 5, kk = e & 31;
        Wsb[0][kk * 129 + n] = (n < AA) ? W[(size_t)n * DD + kk] : 0.f;
    }
    __syncthreads();
    float acc[2][8] = {};
    const int NIT = DD / 32;   // 24
    for (int it = 0; it < NIT; it++) {
        int cur = it & 1;
        float pa[4], pw[8];
        if (it + 1 < NIT) {
            int k1 = (it + 1) * 32;
#pragma unroll
            for (int r = 0; r < 4; r++) {
                int e = tid + 512 * r;
                int m = e >> 5, kk = e & 31, kc = k1 + kk;
                float v = seq[(size_t)(bm + m) * DD + kc];
                pa[r] = fmaf(__ldg(&ga[kc]), (v - rmean[m]) * rinv[m], __ldg(&gb[kc]));
            }
#pragma unroll
            for (int r = 0; r < 8; r++) {
                int e = tid + 512 * r;
                int n = e >> 5, kk = e & 31;
                pw[r] = (n < AA) ? W[(size_t)n * DD + k1 + kk] : 0.f;
            }
        }
        const float* as = Asb[cur];
        const float* ws = Wsb[cur];
#pragma unroll
        for (int kk = 0; kk < 32; kk++) {
            float a0 = as[kk * 65 + ty], a1 = as[kk * 65 + ty + 32];
            float w[8];
#pragma unroll
            for (int j = 0; j < 8; j++) w[j] = ws[kk * 129 + tx + 16 * j];
#pragma unroll
            for (int j = 0; j < 8; j++) {
                acc[0][j] = fmaf(a0, w[j], acc[0][j]);
                acc[1][j] = fmaf(a1, w[j], acc[1][j]);
            }
        }
        if (it + 1 < NIT) {
            float* asn = Asb[1 - cur];
            float* wsn = Wsb[1 - cur];
#pragma unroll
            for (int r = 0; r < 4; r++) { int e = tid + 512 * r; asn[(e & 31) * 65 + (e >> 5)] = pa[r]; }
#pragma unroll
            for (int r = 0; r < 8; r++) { int e = tid + 512 * r; wsn[(e & 31) * 129 + (e >> 5)] = pw[r]; }
        }
        __syncthreads();
    }
#pragma unroll
    for (int i = 0; i < 2; i++) {
        int row = bm + ty + 32 * i;
#pragma unroll
        for (int j = 0; j < 8; j++) {
            int col = tx + 16 * j;
            if (col < AA)
                C[(size_t)row * LDF + col] = acc[i][j] + bias[col];
        }
    }
}

// ---------------- q/k GEMM: grid.y selects weight/out; full-K smem -------
__global__ __launch_bounds__(512) void qk_kernel(
    const float* __restrict__ A,
    const float* __restrict__ qw, const float* __restrict__ qb,
    const float* __restrict__ kw, const float* __restrict__ kb,
    float* __restrict__ qo, float* __restrict__ ko)
{
    extern __shared__ float sm[];
    float* As = sm;               // [r][c] 64x101
    float* Ws = sm + 64 * 101;    // [kk][n] 100x129 (zero-padded n>=100)
    const float* W  = blockIdx.y ? kw : qw;
    const float* bi = blockIdx.y ? kb : qb;
    float* out      = blockIdx.y ? ko : qo;
    int bm = blockIdx.x * 64;
    int tid = threadIdx.x, tx = tid & 15, ty = tid >> 4;
    for (int e = tid; e < 64 * AA; e += 512) {
        int r = e / AA, c = e % AA;
        As[r * 101 + c] = A[(size_t)(bm + r) * LDF + c];
    }
    for (int e = tid; e < AA * AA; e += 512) {
        int n = e / AA, kk = e % AA;
        Ws[kk * 129 + n] = W[e];
    }
    for (int e = tid; e < AA * 28; e += 512) {
        int kk = e / 28, n = AA + e % 28;
        Ws[kk * 129 + n] = 0.f;
    }
    __syncthreads();
    float acc[2][8] = {};
#pragma unroll 4
    for (int kk = 0; kk < AA; kk++) {
        float a0 = As[ty * 101 + kk], a1 = As[(ty + 32) * 101 + kk];
        float w[8];
#pragma unroll
        for (int j = 0; j < 8; j++) w[j] = Ws[kk * 129 + tx + 16 * j];
#pragma unroll
        for (int j = 0; j < 8; j++) {
            acc[0][j] = fmaf(a0, w[j], acc[0][j]);
            acc[1][j] = fmaf(a1, w[j], acc[1][j]);
        }
    }
#pragma unroll
    for (int i = 0; i < 2; i++) {
        int row = bm + ty + 32 * i;
#pragma unroll
        for (int j = 0; j < 8; j++) {
            int col = tx + 16 * j;
            if (col < AA)
                out[(size_t)row * AA + col] = acc[i][j] + bi[col];
        }
    }
}

// ---------------- attention: 4x4 micro-tiles, reg-resident P1/Pc ---------
__global__ void attn2_kernel(const float* __restrict__ q,
                             const float* __restrict__ k,
                             const float* __restrict__ syn,
                             const int* __restrict__ src_mask,
                             const float* __restrict__ pre,
                             float* __restrict__ P1, float* __restrict__ Pc)
{
    extern __shared__ float sm[];
    float* kh   = sm;                     // 512*25
    float* qs   = kh + LL * DKk;          // 16*100
    float* mkf  = qs + 16 * AA;           // 512
    float* redm = mkf + LL;               // 16*4
    float* reds = redm + 64;              // 16*4
    int itile = blockIdx.x, b = blockIdx.y;
    int tid = threadIdx.x;
    int tx = tid & 127, ag = tid >> 7;
    int wg = (tid >> 5) & 3;
    int row0 = itile * 16;

    for (int e = tid; e < 16 * AA; e += 512)
        qs[e] = q[(size_t)(b * LL + row0 + e / AA) * AA + e % AA];
    mkf[tid] = src_mask[b * LL + tid] ? 1.f : 0.f;
    float ch[4] = {__ldg(pre), __ldg(pre + 1), __ldg(pre + 2), __ldg(pre + 3)};
    float p1a[4][4] = {}, pca[4][4] = {};

    for (int h = 0; h < HH; h++) {
        __syncthreads();
        for (int e = tid; e < LL * DKk; e += 512) {
            int j = e / DKk, d = e % DKk;
            kh[e] = k[(size_t)(b * LL + j) * AA + h * DKk + d];
        }
        __syncthreads();
        float s[4][4] = {};
#pragma unroll
        for (int d = 0; d < DKk; d++) {
            float qv[4], kv[4];
#pragma unroll
            for (int ii = 0; ii < 4; ii++) qv[ii] = qs[(ag + 4 * ii) * AA + h * DKk + d];
#pragma unroll
            for (int jj = 0; jj < 4; jj++) kv[jj] = kh[(tx + 128 * jj) * DKk + d];
#pragma unroll
            for (int ii = 0; ii < 4; ii++)
#pragma unroll
                for (int jj = 0; jj < 4; jj++)
                    s[ii][jj] = fmaf(qv[ii], kv[jj], s[ii][jj]);
        }
        const float* synb = syn + ((size_t)(b * HH + h) * LL + row0) * LL;
        float mloc[4];
#pragma unroll
        for (int ii = 0; ii < 4; ii++) {
            mloc[ii] = -1e30f;
#pragma unroll
            for (int jj = 0; jj < 4; jj++) {
                int j = tx + 128 * jj;
                float v = (mkf[j] != 0.f) ? s[ii][jj] * 0.2f : -1e9f;
                v += synb[(size_t)(ag + 4 * ii) * LL + j];
                s[ii][jj] = v;
                mloc[ii] = fmaxf(mloc[ii], v);
            }
        }
        for (int o = 16; o; o >>= 1)
#pragma unroll
            for (int ii = 0; ii < 4; ii++)
                mloc[ii] = fmaxf(mloc[ii], __shfl_xor_sync(0xffffffffu, mloc[ii], o));
        if ((tid & 31) == 0)
#pragma unroll
            for (int ii = 0; ii < 4; ii++)
                redm[(ag + 4 * ii) * 4 + wg] = mloc[ii];
        __syncthreads();
        float m[4], ssum[4];
#pragma unroll
        for (int ii = 0; ii < 4; ii++) {
            int r = ag + 4 * ii;
            m[ii] = fmaxf(fmaxf(redm[r * 4], redm[r * 4 + 1]),
                          fmaxf(redm[r * 4 + 2], redm[r * 4 + 3]));
            ssum[ii] = 0.f;
#pragma unroll
            for (int jj = 0; jj < 4; jj++) {
                float e = __expf(s[ii][jj] - m[ii]);
                s[ii][jj] = e;
                ssum[ii] += e;
            }
        }
        for (int o = 16; o; o >>= 1)
#pragma unroll
            for (int ii = 0; ii < 4; ii++)
                ssum[ii] += __shfl_xor_sync(0xffffffffu, ssum[ii], o);
        if ((tid & 31) == 0)
#pragma unroll
            for (int ii = 0; ii < 4; ii++)
                reds[(ag + 4 * ii) * 4 + wg] = ssum[ii];
        __syncthreads();
#pragma unroll
        for (int ii = 0; ii < 4; ii++) {
            int r = ag + 4 * ii;
            float inv = 1.f / (reds[r * 4] + reds[r * 4 + 1] + reds[r * 4 + 2] + reds[r * 4 + 3]);
#pragma unroll
            for (int jj = 0; jj < 4; jj++) {
                float a = s[ii][jj] * inv;
                p1a[ii][jj] += a;
                pca[ii][jj] += ch[h] * a;
            }
        }
    }
#pragma unroll
    for (int ii = 0; ii < 4; ii++) {
        size_t off = ((size_t)(b * LL) + row0 + ag + 4 * ii) * LL + tx;
#pragma unroll
        for (int jj = 0; jj < 4; jj++) {
            P1[off + 128 * jj] = p1a[ii][jj];
            Pc[off + 128 * jj] = pca[ii][jj];
        }
    }
}

// ---------------- fused GCN layer, 512 thr, double-buffered P@X ----------
__global__ __launch_bounds__(512) void layer_kernel(
    const float* __restrict__ P,
    const float* __restrict__ Xin,
    const float* __restrict__ Ww,
    const float* __restrict__ Wb,
    float* __restrict__ Xout,
    int mode,
    const float* __restrict__ V,
    const float* __restrict__ corrS,
    const float* __restrict__ pre)
{
    extern __shared__ float sm[];
    float* Axs = sm;                                   // 64*101
    float* buf = sm + 64 * 101;                        // 12900 floats
    float* Psb[2] = { buf, buf + 6208 };               // [kk][m] 32x65
    float* Xsb[2] = { buf + 2080, buf + 6208 + 2080 }; // [kk][d] 32x129
    float* Ws2 = buf;                                  // phase 2: [kk][n] 100x129
    int bi = blockIdx.x * 64, b = blockIdx.y;
    int tid = threadIdx.x, tx = tid & 15, ty = tid >> 4;   // ty 0..31
    const float* Pb = P + (size_t)b * LL * LL;
    const float* Xb = Xin + (size_t)b * LL * LDF;
    // stage tile 0
    for (int e = tid; e < 64 * 32; e += 512) {
        int m = e >> 5, kk = e & 31;
        Psb[0][kk * 65 + m] = Pb[(size_t)(bi + m) * LL + kk];
    }
    for (int e = tid; e < 32 * 128; e += 512) {
        int kk = e >> 7, d = e & 127;
        Xsb[0][kk * 129 + d] = (d < AA) ? Xb[(size_t)kk * LDF + d] : 0.f;
    }
    __syncthreads();
    float acc[2][8] = {};
    const int NIT = LL / 32;   // 16
    for (int it = 0; it < NIT; it++) {
        int cur = it & 1;
        float pa[4], pw[8];
        if (it + 1 < NIT) {
            int k1 = (it + 1) * 32;
#pragma unroll
            for (int r = 0; r < 4; r++) {
                int e = tid + 512 * r;
                int m = e >> 5, kk = e & 31;
                pa[r] = Pb[(size_t)(bi + m) * LL + k1 + kk];
            }
#pragma unroll
            for (int r = 0; r < 8; r++) {
                int e = tid + 512 * r;
                int kk = e >> 7, d = e & 127;
                pw[r] = (d < AA) ? Xb[(size_t)(k1 + kk) * LDF + d] : 0.f;
            }
        }
        const float* ps = Psb[cur];
        const float* xs = Xsb[cur];
#pragma unroll
        for (int kk = 0; kk < 32; kk++) {
            float a0 = ps[kk * 65 + ty], a1 = ps[kk * 65 + ty + 32];
            float x[8];
#pragma unroll
            for (int j = 0; j < 8; j++) x[j] = xs[kk * 129 + tx + 16 * j];
#pragma unroll
            for (int j = 0; j < 8; j++) {
                acc[0][j] = fmaf(a0, x[j], acc[0][j]);
                acc[1][j] = fmaf(a1, x[j], acc[1][j]);
            }
        }
        if (it + 1 < NIT) {
            float* psn = Psb[1 - cur];
            float* xsn = Xsb[1 - cur];
#pragma unroll
            for (int r = 0; r < 4; r++) { int e = tid + 512 * r; psn[(e & 31) * 65 + (e >> 5)] = pa[r]; }
#pragma unroll
            for (int r = 0; r < 8; r++) { int e = tid + 512 * r; xsn[(e & 127) + 129 * (e >> 7)] = pw[r]; }
        }
        __syncthreads();
    }
    // corrections + Ax -> smem
    float Cb = mode ? pre[204] : 0.f;
#pragma unroll
    for (int i = 0; i < 2; i++) {
        int row = ty + 32 * i;
        float vr = mode ? (V[b * LL + bi + row] + Cb) : 0.f;
#pragma unroll
        for (int j = 0; j < 8; j++) {
            int col = tx + 16 * j;
            if (col < AA) {
                float r = acc[i][j];
                if (mode)
                    r += corrS[b * 2 * AA + col] + vr * corrS[b * 2 * AA + AA + col];
                Axs[row * 101 + col] = r * 0.25f;
            }
        }
    }
    // phase 2: full W (aliases buf; safe after last sync above)
    for (int e = tid; e < AA * AA; e += 512) {
        int n = e / AA, kk = e % AA;
        Ws2[kk * 129 + n] = Ww[e];
    }
    for (int e = tid; e < AA * 28; e += 512) {
        int kk = e / 28, n = AA + e % 28;
        Ws2[kk * 129 + n] = 0.f;
    }
    __syncthreads();
    float acc2[2][8] = {};
#pragma unroll 4
    for (int kk = 0; kk < AA; kk++) {
        float a0 = Axs[ty * 101 + kk], a1 = Axs[(ty + 32) * 101 + kk];
        float w[8];
#pragma unroll
        for (int j = 0; j < 8; j++) w[j] = Ws2[kk * 129 + tx + 16 * j];
#pragma unroll
        for (int j = 0; j < 8; j++) {
            acc2[0][j] = fmaf(a0, w[j], acc2[0][j]);
            acc2[1][j] = fmaf(a1, w[j], acc2[1][j]);
        }
    }
#pragma unroll
    for (int i = 0; i < 2; i++) {
        size_t row = (size_t)b * LL + bi + ty + 32 * i;
#pragma unroll
        for (int j = 0; j < 8; j++) {
            int col = tx + 16 * j;
            if (col < AA)
                Xout[row * LDF + col] = fmaxf(acc2[i][j] + Wb[col], 0.f);
        }
    }
}

// ---------------- U, V per row ----------------
__global__ void uv_kernel(const float* __restrict__ x1,
                          const float* __restrict__ pre,
                          float* __restrict__ U, float* __restrict__ V)
{
    __shared__ float b1s[AA], b2s[AA];
    int tid = threadIdx.x;
    for (int e = tid; e < AA; e += 256) { b1s[e] = pre[4 + e]; b2s[e] = pre[104 + e]; }
    __syncthreads();
    int row = blockIdx.x * 8 + (tid >> 5);
    int lane = tid & 31;
    const float* xr = x1 + (size_t)row * LDF;
    float u = 0.f, v = 0.f;
    for (int d = lane; d < AA; d += 32) {
        float xv = xr[d];
        u = fmaf(xv, b1s[d], u);
        v = fmaf(xv, b2s[d], v);
    }
    for (int o = 16; o; o >>= 1) {
        u += __shfl_xor_sync(0xffffffffu, u, o);
        v += __shfl_xor_sync(0xffffffffu, v, o);
    }
    if (lane == 0) { U[row] = u; V[row] = v; }
}

// ---------------- corr / S ----------------
__global__ void corrS_kernel(const float* __restrict__ x1,
                             const float* __restrict__ U,
                             float* __restrict__ corrS)
{
    __shared__ float sc[2][128], ss[2][128];
    int b = blockIdx.x, tid = threadIdx.x;
    int d = tid & 127, half = tid >> 7;
    float c = 0.f, s = 0.f;
    if (d < AA) {
        for (int j = half; j < LL; j += 2) {
            float xv = x1[((size_t)b * LL + j) * LDF + d];
            c = fmaf(U[b * LL + j], xv, c);
            s += xv;
        }
    }
    sc[half][d] = c; ss[half][d] = s;
    __syncthreads();
    if (half == 0 && d < AA) {
        corrS[b * 2 * AA + d]      = sc[0][d] + sc[1][d];
        corrS[b * 2 * AA + AA + d] = ss[0][d] + ss[1][d];
    }
}

// ---------------- agg GEMM, 512 thr, double-buffered + fused pool --------
__global__ __launch_bounds__(512) void gemm_agg(
    const float* __restrict__ A,       // feats, ld 300
    const float* __restrict__ W,       // agg_w, 100 x 300
    const float* __restrict__ bias,
    float* __restrict__ pool)
{
    extern __shared__ float sm[];
    float* Asb[2] = { sm, sm + 2080 };
    float* Wsb[2] = { sm + 4160, sm + 4160 + 4128 };
    float* red = sm + 12416;           // 32x129
    int bm = blockIdx.x * 64;
    int b = bm >> 9;
    int tid = threadIdx.x, tx = tid & 15, ty = tid >> 4;
    // stage tile 0 (kk<32 all valid, K=300)
    for (int e = tid; e < 64 * 32; e += 512) {
        int m = e >> 5, kk = e & 31;
        Asb[0][kk * 65 + m] = A[(size_t)(bm + m) * LDF + kk];
    }
    for (int e = tid; e < 128 * 32; e += 512) {
        int n = e >> 5, kk = e & 31;
        Wsb[0][kk * 129 + n] = (n < AA) ? W[(size_t)n * LDF + kk] : 0.f;
    }
    __syncthreads();
    float acc[2][8] = {};
    const int NIT = (LDF + 31) / 32;   // 10 (last partial, zero-filled)
    for (int it = 0; it < NIT; it++) {
        int cur = it & 1;
        float pa[4], pw[8];
        if (it + 1 < NIT) {
            int k1 = (it + 1) * 32;
#pragma unroll
            for (int r = 0; r < 4; r++) {
                int e = tid + 512 * r;
                int m = e >> 5, kk = e & 31;
                pa[r] = (k1 + kk < LDF) ? A[(size_t)(bm + m) * LDF + k1 + kk] : 0.f;
            }
#pragma unroll
            for (int r = 0; r < 8; r++) {
                int e = tid + 512 * r;
                int n = e >> 5, kk = e & 31;
                pw[r] = (n < AA && k1 + kk < LDF) ? W[(size_t)n * LDF + k1 + kk] : 0.f;
            }
        }
        const float* as = Asb[cur];
        const float* ws = Wsb[cur];
#pragma unroll
        for (int kk = 0; kk < 32; kk++) {
            float a0 = as[kk * 65 + ty], a1 = as[kk * 65 + ty + 32];
            float w[8];
#pragma unroll
            for (int j = 0; j < 8; j++) w[j] = ws[kk * 129 + tx + 16 * j];
#pragma unroll
            for (int j = 0; j < 8; j++) {
                acc[0][j] = fmaf(a0, w[j], acc[0][j]);
                acc[1][j] = fmaf(a1, w[j], acc[1][j]);
            }
        }
        if (it + 1 < NIT) {
            float* asn = Asb[1 - cur];
            float* wsn = Wsb[1 - cur];
#pragma unroll
            for (int r = 0; r < 4; r++) { int e = tid + 512 * r; asn[(e & 31) * 65 + (e >> 5)] = pa[r]; }
#pragma unroll
            for (int r = 0; r < 8; r++) { int e = tid + 512 * r; wsn[(e & 31) * 129 + (e >> 5)] = pw[r]; }
        }
        __syncthreads();
    }
    // relu + per-block column sums -> atomic pool
#pragma unroll
    for (int j = 0; j < 8; j++) {
        int col = tx + 16 * j;
        float bcol = (col < AA) ? bias[col] : 0.f;
        float p = fmaxf(acc[0][j] + bcol, 0.f) + fmaxf(acc[1][j] + bcol, 0.f);
        red[ty * 129 + col] = p;
    }
    __syncthreads();
    if (ty == 0) {
#pragma unroll
        for (int j = 0; j < 8; j++) {
            int col = tx + 16 * j;
            if (col < AA) {
                float s = 0.f;
#pragma unroll
                for (int t = 0; t < 32; t++) s += red[t * 129 + col];
                atomicAdd(&pool[b * AA + col], s);
            }
        }
    }
}

// ---------------- logits ----------------
__global__ void logits_kernel(const float* __restrict__ pool,
                              const int* __restrict__ mask_ids,
                              const float* __restrict__ cls_w,
                              const float* __restrict__ cls_b,
                              float* __restrict__ out)
{
    __shared__ float linv[BB];
    __shared__ float pr[BB * AA];
    __shared__ float cw[PP * AA];
    int tid = threadIdx.x;              // 512
    int warp = tid >> 5, lane = tid & 31;
    if (warp < BB) {
        int ms = 0;
#pragma unroll
        for (int t = 0; t < 16; t++) ms += mask_ids[warp * LL + lane + 32 * t];
        for (int o = 16; o; o >>= 1) ms += __shfl_xor_sync(0xffffffffu, ms, o);
        if (lane == 0) linv[warp] = 1.f / fmaxf((float)ms, 1.f);
    }
    for (int e = tid; e < BB * AA; e += 512) pr[e] = pool[e];
    for (int e = tid; e < PP * AA; e += 512) cw[e] = cls_w[e];
    __syncthreads();
    if (tid < BB * PP) {
        int b = tid / PP, p = tid % PP;
        float s0 = 0.f, s1 = 0.f, s2 = 0.f, s3 = 0.f;
#pragma unroll
        for (int d = 0; d < AA; d += 4) {
            s0 = fmaf(pr[b * AA + d + 0], cw[p * AA + d + 0], s0);
            s1 = fmaf(pr[b * AA + d + 1], cw[p * AA + d + 1], s1);
            s2 = fmaf(pr[b * AA + d + 2], cw[p * AA + d + 2], s2);
            s3 = fmaf(pr[b * AA + d + 3], cw[p * AA + d + 3], s3);
        }
        out[tid] = cls_b[p] + linv[b] * (s0 + s1 + s2 + s3);
    }
}

// ---------------- launch ----------------
extern "C" void kernel_launch(void* const* d_in, const int* in_sizes, int n_in,
                              void* d_out, int out_size)
{
    const float* seq      = (const float*)d_in[0];
    const float* syn      = (const float*)d_in[1];
    const float* ln_a     = (const float*)d_in[2];
    const float* ln_b     = (const float*)d_in[3];
    const float* Wxx_w    = (const float*)d_in[4];
    const float* Wxx_b    = (const float*)d_in[5];
    const float* q_w      = (const float*)d_in[6];
    const float* q_b      = (const float*)d_in[7];
    const float* k_w      = (const float*)d_in[8];
    const float* k_b      = (const float*)d_in[9];
    const float* W_w      = (const float*)d_in[10];
    const float* W_b      = (const float*)d_in[11];
    const float* Wx_w     = (const float*)d_in[12];
    const float* Wx_b     = (const float*)d_in[13];
    const float* agg_w    = (const float*)d_in[14];
    const float* agg_b    = (const float*)d_in[15];
    const float* cls_w    = (const float*)d_in[16];
    const float* cls_b    = (const float*)d_in[17];
    const int*   mask_ids = (const int*)d_in[18];
    const int*   src_mask = (const int*)d_in[19];
    float* out = (float*)d_out;

    float *feats, *q, *k, *P1, *Pc, *U, *V, *corrS, *pre, *pool, *mean, *inv;
    cudaGetSymbolAddress((void**)&feats, g_feats);
    cudaGetSymbolAddress((void**)&q,     g_q);
    cudaGetSymbolAddress((void**)&k,     g_k);
    cudaGetSymbolAddress((void**)&P1,    g_P1);
    cudaGetSymbolAddress((void**)&Pc,    g_Pc);
    cudaGetSymbolAddress((void**)&U,     g_U);
    cudaGetSymbolAddress((void**)&V,     g_V);
    cudaGetSymbolAddress((void**)&corrS, g_corrS);
    cudaGetSymbolAddress((void**)&pre,   g_pre);
    cudaGetSymbolAddress((void**)&pool,  g_pool);
    cudaGetSymbolAddress((void**)&mean,  g_mean);
    cudaGetSymbolAddress((void**)&inv,   g_inv);

    const int M = BB * LL;           // 8192
    const int GM = M / 64;           // 128

    const int GEMMLN_SMEM = 12416 * 4;                               // 49,664
    const int QK_SMEM     = (64 * 101 + 100 * 129) * 4;              // 77,456
    const int ATTN_SMEM   = (LL * DKk + 16 * AA + LL + 128) * 4;
    const int LAYER_SMEM  = (64 * 101 + 100 * 129) * 4;              // 77,456
    const int AGG_SMEM    = (12416 + 32 * 129) * 4;                  // 66,176
    cudaFuncSetAttribute(gemm_ln,      cudaFuncAttributeMaxDynamicSharedMemorySize, GEMMLN_SMEM);
    cudaFuncSetAttribute(qk_kernel,    cudaFuncAttributeMaxDynamicSharedMemorySize, QK_SMEM);
    cudaFuncSetAttribute(attn2_kernel, cudaFuncAttributeMaxDynamicSharedMemorySize, ATTN_SMEM);
    cudaFuncSetAttribute(layer_kernel, cudaFuncAttributeMaxDynamicSharedMemorySize, LAYER_SMEM);
    cudaFuncSetAttribute(gemm_agg,     cudaFuncAttributeMaxDynamicSharedMemorySize, AGG_SMEM);

    // 0) folded weights + zero pool
    precomp_kernel<<<1, 256>>>(Wx_w, Wx_b, pre, pool);
    // 1) LN stats
    ln_stats<<<M / 8, 256>>>(seq, mean, inv);
    // 2) x = LN(seq) @ Wxx^T + b
    gemm_ln<<<GM, 512, GEMMLN_SMEM>>>(seq, ln_a, ln_b, mean, inv, Wxx_w, Wxx_b, feats);
    // 3) q & k (grid.y selects)
    qk_kernel<<<dim3(GM, 2), 512, QK_SMEM>>>(feats, q_w, q_b, k_w, k_b, q, k);
    // 4) attention -> P1, Pc
    attn2_kernel<<<dim3(LL / 16, BB), 512, ATTN_SMEM>>>(q, k, syn, src_mask, pre, P1, Pc);
    // 5) layer 1 fused
    layer_kernel<<<dim3(LL / 64, BB), 512, LAYER_SMEM>>>(P1, feats, W_w, W_b, feats + AA,
                                                         0, nullptr, nullptr, nullptr);
    // 6) rank-1 corrections
    uv_kernel<<<M / 8, 256>>>(feats + AA, pre, U, V);
    corrS_kernel<<<BB, 256>>>(feats + AA, U, corrS);
    // 7) layer 2 fused
    layer_kernel<<<dim3(LL / 64, BB), 512, LAYER_SMEM>>>(Pc, feats + AA, W_w, W_b, feats + 2 * AA,
                                                         1, V, corrS, pre);
    // 8) aggregate + relu + masked mean pool
    gemm_agg<<<GM, 512, AGG_SMEM>>>(feats, agg_w, agg_b, pool);
    // 9) logits
    logits_kernel<<<1, 512>>>(pool, mask_ids, cls_w, cls_b, out);
}

// round 14
// speedup vs baseline: 3.0304x; 1.6731x over previous
#include <cuda_runtime.h>
#include <cuda_fp16.h>
#include <math.h>

constexpr int BB = 16, LL = 512, DD = 768, HH = 4, AA = 100, DKk = 25, PP = 3;
constexpr int LDW_X = HH + 2 * AA;     // 204
constexpr int LDQ  = 112;              // q/k half row stride
constexpr int LDFH = 320;              // featsh row stride (x|x1|x2|zeros)
constexpr float EPSf = 1e-6f;

using u32 = unsigned int;

// ---------------- device scratch (zero-initialized) ----------------
__device__ __align__(16) __half g_featsh[BB * LL * LDFH];  // cols 0-99 x,100-199 x1,200-299 x2, rest 0
__device__ __align__(16) __half g_xT [BB * LDQ * LL];      // x^T  [b][d][j], rows 100..111 stay 0
__device__ __align__(16) __half g_x1T[BB * LDQ * LL];
__device__ __align__(16) __half g_qh [BB * LL * LDQ];
__device__ __align__(16) __half g_kh [BB * LL * LDQ];
__device__ __align__(16) __half g_P1h[BB * LL * LL];       // sum_h adj_h      (8 MB)
__device__ __align__(16) __half g_Pch[BB * LL * LL];       // sum_h c_h adj_h  (8 MB)
__device__ float g_x1   [BB * LL * AA];                    // fp32 x1 for uv/corr
__device__ float g_U[BB * LL], g_V[BB * LL];
__device__ float g_corrS[BB * 2 * AA];
__device__ float g_pre[256];
__device__ float g_pool[BB * AA];
__device__ float g_mean[BB * LL], g_inv[BB * LL];

// ---------------- mma.sync m16n8k16 f16 helpers ----------------
__device__ __forceinline__ void mma_f16(float c[4], const u32 a[4], const u32 b[2])
{
    asm volatile(
        "mma.sync.aligned.m16n8k16.row.col.f32.f16.f16.f32 "
        "{%0,%1,%2,%3}, {%4,%5,%6,%7}, {%8,%9}, {%0,%1,%2,%3};\n"
        : "+f"(c[0]), "+f"(c[1]), "+f"(c[2]), "+f"(c[3])
        : "r"(a[0]), "r"(a[1]), "r"(a[2]), "r"(a[3]), "r"(b[0]), "r"(b[1]));
}
// A tile: row-major [row][k] halves, stride ld (k-pairs contiguous)
__device__ __forceinline__ void ldfrag_a(u32 a[4], const __half* S, int row0, int k0, int lane, int ld)
{
    int r = lane >> 2, c = (lane & 3) * 2;
    a[0] = *(const u32*)(S + (row0 + r    ) * ld + k0 + c    );
    a[1] = *(const u32*)(S + (row0 + r + 8) * ld + k0 + c    );
    a[2] = *(const u32*)(S + (row0 + r    ) * ld + k0 + c + 8);
    a[3] = *(const u32*)(S + (row0 + r + 8) * ld + k0 + c + 8);
}
// B tile stored as B^T row-major [n][k] halves, stride ld
__device__ __forceinline__ void ldfrag_b(u32 b[2], const __half* S, int n0, int k0, int lane, int ld)
{
    int r = lane >> 2, c = (lane & 3) * 2;
    b[0] = *(const u32*)(S + (n0 + r) * ld + k0 + c    );
    b[1] = *(const u32*)(S + (n0 + r) * ld + k0 + c + 8);
}

// ---------------- precompute: c, b1s, b2s, Cb + zero pool ----------------
__global__ void precomp_kernel(const float* __restrict__ Wxw,
                               const float* __restrict__ Wxb,
                               float* __restrict__ pre, float* __restrict__ pool)
{
    int t = threadIdx.x;
    if (t < 4) {
        float s = 0.f;
        for (int g = 0; g < HH; g++) s += Wxw[g * LDW_X + t];
        pre[t] = s;
    } else if (t < 104) {
        int d = t - 4; float s = 0.f;
        for (int g = 0; g < HH; g++) s += Wxw[g * LDW_X + HH + d];
        pre[t] = s;
    } else if (t < 204) {
        int d = t - 104; float s = 0.f;
        for (int g = 0; g < HH; g++) s += Wxw[g * LDW_X + HH + AA + d];
        pre[t] = s;
    } else if (t == 204) {
        pre[204] = Wxb[0] + Wxb[1] + Wxb[2] + Wxb[3];
    }
    for (int e = t; e < BB * AA; e += 256) pool[e] = 0.f;
}

// ---------------- LN stats ----------------
__global__ void ln_stats(const float* __restrict__ x,
                         float* __restrict__ mean, float* __restrict__ inv)
{
    int row = blockIdx.x * 8 + (threadIdx.x >> 5);
    int lane = threadIdx.x & 31;
    const float4* xr = (const float4*)(x + (size_t)row * DD);
    float s = 0.f, s2 = 0.f;
#pragma unroll
    for (int d = lane; d < DD / 4; d += 32) {
        float4 v = xr[d];
        s += v.x + v.y + v.z + v.w;
        s2 = fmaf(v.x, v.x, s2); s2 = fmaf(v.y, v.y, s2);
        s2 = fmaf(v.z, v.z, s2); s2 = fmaf(v.w, v.w, s2);
    }
    for (int o = 16; o; o >>= 1) {
        s  += __shfl_xor_sync(0xffffffffu, s,  o);
        s2 += __shfl_xor_sync(0xffffffffu, s2, o);
    }
    if (lane == 0) {
        float m   = s / (float)DD;
        float var = (s2 - (float)DD * m * m) / (float)(DD - 1);
        mean[row] = m;
        inv[row]  = 1.f / (sqrtf(fmaxf(var, 0.f)) + EPSf);
    }
}

// ---------------- x = LN(seq) @ Wxx^T + b  (fp16 mma, fp32 accum) --------
__global__ __launch_bounds__(256) void gemm_ln_h(
    const float* __restrict__ seq,
    const float* __restrict__ ga, const float* __restrict__ gb,
    const float* __restrict__ mean, const float* __restrict__ inv,
    const float* __restrict__ W, const float* __restrict__ bias,
    __half* __restrict__ featsh, __half* __restrict__ xT)
{
    extern __shared__ __half smh[];
    __half* Ab[2] = { smh,        smh + 7040 };        // 64x40
    __half* Bb[2] = { smh + 2560, smh + 7040 + 2560 }; // 112x40
    __shared__ float rmean[64], rinv[64], bsh[112];
    int bm = blockIdx.x * 64;
    int tid = threadIdx.x, lane = tid & 31, warp = tid >> 5;
    int wm = warp >> 1, wn = warp & 1;
    if (tid < 64) { rmean[tid] = mean[bm + tid]; rinv[tid] = inv[bm + tid]; }
    if (tid < 112) bsh[tid] = (tid < AA) ? bias[tid] : 0.f;
    __syncthreads();
    // stage chunk 0
    for (int e = tid; e < 2048; e += 256) {
        int m = e >> 5, kk = e & 31;
        float v = seq[(size_t)(bm + m) * DD + kk];
        Ab[0][m * 40 + kk] = __float2half(fmaf(ga[kk], (v - rmean[m]) * rinv[m], gb[kk]));
    }
    for (int e = tid; e < 3584; e += 256) {
        int n = e >> 5, kk = e & 31;
        Bb[0][n * 40 + kk] = __float2half((n < AA) ? W[(size_t)n * DD + kk] : 0.f);
    }
    __syncthreads();
    float acc[7][4] = {};
    const int NIT = DD / 32;   // 24
    for (int it = 0; it < NIT; it++) {
        int cur = it & 1;
        float pa[8], pb[14];
        if (it + 1 < NIT) {
            int k1 = (it + 1) * 32;
#pragma unroll
            for (int r2 = 0; r2 < 8; r2++) {
                int e = tid + 256 * r2, m = e >> 5, kk = e & 31, kc = k1 + kk;
                float v = seq[(size_t)(bm + m) * DD + kc];
                pa[r2] = fmaf(ga[kc], (v - rmean[m]) * rinv[m], gb[kc]);
            }
#pragma unroll
            for (int r2 = 0; r2 < 14; r2++) {
                int e = tid + 256 * r2, n = e >> 5, kk = e & 31;
                pb[r2] = (n < AA) ? W[(size_t)n * DD + k1 + kk] : 0.f;
            }
        }
        const __half* As = Ab[cur];
        const __half* Bs = Bb[cur];
#pragma unroll
        for (int ks = 0; ks < 32; ks += 16) {
            u32 a[4], b[2];
            ldfrag_a(a, As, wm * 16, ks, lane, 40);
#pragma unroll
            for (int t = 0; t < 7; t++) {
                ldfrag_b(b, Bs, wn * 56 + 8 * t, ks, lane, 40);
                mma_f16(acc[t], a, b);
            }
        }
        if (it + 1 < NIT) {
            __half* An = Ab[1 - cur];
            __half* Bn = Bb[1 - cur];
#pragma unroll
            for (int r2 = 0; r2 < 8; r2++) { int e = tid + 256 * r2; An[(e >> 5) * 40 + (e & 31)] = __float2half(pa[r2]); }
#pragma unroll
            for (int r2 = 0; r2 < 14; r2++) { int e = tid + 256 * r2; Bn[(e >> 5) * 40 + (e & 31)] = __float2half(pb[r2]); }
        }
        __syncthreads();
    }
    int r = lane >> 2, cb = (lane & 3) * 2;
#pragma unroll
    for (int t = 0; t < 7; t++) {
        int col = wn * 56 + 8 * t + cb;
        if (col >= AA) continue;
        int g0 = bm + wm * 16 + r, g1 = g0 + 8;
        float o0 = acc[t][0] + bsh[col], o1 = acc[t][1] + bsh[col + 1];
        float o2 = acc[t][2] + bsh[col], o3 = acc[t][3] + bsh[col + 1];
        *(half2*)&featsh[(size_t)g0 * LDFH + col] = __floats2half2_rn(o0, o1);
        *(half2*)&featsh[(size_t)g1 * LDFH + col] = __floats2half2_rn(o2, o3);
        int b0i = g0 >> 9, j0 = g0 & 511, b1i = g1 >> 9, j1 = g1 & 511;
        xT[((size_t)b0i * LDQ + col    ) * LL + j0] = __float2half(o0);
        xT[((size_t)b0i * LDQ + col + 1) * LL + j0] = __float2half(o1);
        xT[((size_t)b1i * LDQ + col    ) * LL + j1] = __float2half(o2);
        xT[((size_t)b1i * LDQ + col + 1) * LL + j1] = __float2half(o3);
    }
}

// ---------------- q,k = x @ {q_w,k_w}^T + bias (fp16 mma, shared A) ------
__global__ __launch_bounds__(256) void qk_h(
    const __half* __restrict__ featsh,
    const float* __restrict__ qw, const float* __restrict__ qb,
    const float* __restrict__ kw, const float* __restrict__ kb,
    __half* __restrict__ qh, __half* __restrict__ kh)
{
    extern __shared__ __half smh[];
    __half* Ash = smh;             // 64 x 120
    __half* Wq  = smh + 7680;      // 112 x 120
    __half* Wk  = Wq + 13440;      // 112 x 120
    __shared__ float bqs[112], bks[112];
    int bm = blockIdx.x * 64;
    int tid = threadIdx.x, lane = tid & 31, warp = tid >> 5;
    int wm = warp >> 1, wn = warp & 1;
    if (tid < 112) { bqs[tid] = (tid < AA) ? qb[tid] : 0.f; bks[tid] = (tid < AA) ? kb[tid] : 0.f; }
    for (int e = tid; e < 64 * 56; e += 256) {      // u32 copies of featsh rows (cols 0..111)
        int m = e / 56, cp = e % 56;
        *(u32*)&Ash[m * 120 + 2 * cp] = *(const u32*)&featsh[(size_t)(bm + m) * LDFH + 2 * cp];
    }
    for (int e = tid; e < 112 * 112; e += 256) {
        int n = e / 112, kk = e % 112;
        bool v = (n < AA) && (kk < AA);
        Wq[n * 120 + kk] = __float2half(v ? qw[n * AA + kk] : 0.f);
        Wk[n * 120 + kk] = __float2half(v ? kw[n * AA + kk] : 0.f);
    }
    __syncthreads();
    float aq[7][4] = {}, ak[7][4] = {};
#pragma unroll
    for (int ks = 0; ks < 7; ks++) {
        u32 a[4], b[2];
        ldfrag_a(a, Ash, wm * 16, 16 * ks, lane, 120);
#pragma unroll
        for (int t = 0; t < 7; t++) {
            ldfrag_b(b, Wq, wn * 56 + 8 * t, 16 * ks, lane, 120);
            mma_f16(aq[t], a, b);
            ldfrag_b(b, Wk, wn * 56 + 8 * t, 16 * ks, lane, 120);
            mma_f16(ak[t], a, b);
        }
    }
    int r = lane >> 2, cb = (lane & 3) * 2;
#pragma unroll
    for (int t = 0; t < 7; t++) {
        int col = wn * 56 + 8 * t + cb;
        if (col >= AA) continue;
        int g0 = bm + wm * 16 + r, g1 = g0 + 8;
        *(half2*)&qh[(size_t)g0 * LDQ + col] = __floats2half2_rn(aq[t][0] + bqs[col], aq[t][1] + bqs[col + 1]);
        *(half2*)&qh[(size_t)g1 * LDQ + col] = __floats2half2_rn(aq[t][2] + bqs[col], aq[t][3] + bqs[col + 1]);
        *(half2*)&kh[(size_t)g0 * LDQ + col] = __floats2half2_rn(ak[t][0] + bks[col], ak[t][1] + bks[col + 1]);
        *(half2*)&kh[(size_t)g1 * LDQ + col] = __floats2half2_rn(ak[t][2] + bks[col], ak[t][3] + bks[col + 1]);
    }
}

// ---------------- attention (mma scores) -> P1h, Pch ----------------
__global__ __launch_bounds__(512) void attn3_kernel(
    const __half* __restrict__ qh, const __half* __restrict__ kh,
    const float* __restrict__ syn, const int* __restrict__ src_mask,
    const float* __restrict__ pre,
    __half* __restrict__ P1, __half* __restrict__ Pc)
{
    extern __shared__ float smf[];
    float* mkf  = smf;          // 512
    float* redm = smf + 512;    // 16x16
    float* reds = smf + 768;    // 16x16
    __half* khs = (__half*)(smf + 1024);   // 512 x 40
    __half* qss = khs + 512 * 40;          // 16 x 40
    int itile = blockIdx.x, b = blockIdx.y;
    int tid = threadIdx.x, lane = tid & 31, warp = tid >> 5;
    int row0 = itile * 16;
    int n0 = warp * 32;
    int r = lane >> 2, cb = (lane & 3) * 2;

    mkf[tid] = src_mask[b * LL + tid] ? 1.f : 0.f;
    float ch[4] = { __ldg(pre), __ldg(pre + 1), __ldg(pre + 2), __ldg(pre + 3) };
    float p1a[4][4] = {}, pca[4][4] = {};

    for (int h = 0; h < HH; h++) {
        for (int e = tid; e < 512 * 32; e += 512) {
            int j = e >> 5, d = e & 31;
            khs[j * 40 + d] = (d < DKk) ? kh[(size_t)(b * LL + j) * LDQ + h * DKk + d]
                                        : __float2half(0.f);
        }
        {
            int j = tid >> 5, d = tid & 31;
            qss[j * 40 + d] = (d < DKk) ? qh[(size_t)(b * LL + row0 + j) * LDQ + h * DKk + d]
                                        : __float2half(0.f);
        }
        __syncthreads();
        float s[4][4] = {};
#pragma unroll
        for (int ks = 0; ks < 32; ks += 16) {
            u32 a[4], bfr[2];
            ldfrag_a(a, qss, 0, ks, lane, 40);
#pragma unroll
            for (int t = 0; t < 4; t++) {
                ldfrag_b(bfr, khs, n0 + 8 * t, ks, lane, 40);
                mma_f16(s[t], a, bfr);
            }
        }
        float mx0 = -1e30f, mx1 = -1e30f;
#pragma unroll
        for (int t = 0; t < 4; t++) {
            int col = n0 + 8 * t + cb;
            float2 sy0 = *(const float2*)&syn[(((size_t)(b * HH + h)) * LL + row0 + r    ) * LL + col];
            float2 sy1 = *(const float2*)&syn[(((size_t)(b * HH + h)) * LL + row0 + r + 8) * LL + col];
            float m0 = mkf[col], m1 = mkf[col + 1];
            float v0 = ((m0 != 0.f) ? s[t][0] * 0.2f : -1e9f) + sy0.x;
            float v1 = ((m1 != 0.f) ? s[t][1] * 0.2f : -1e9f) + sy0.y;
            float v2 = ((m0 != 0.f) ? s[t][2] * 0.2f : -1e9f) + sy1.x;
            float v3 = ((m1 != 0.f) ? s[t][3] * 0.2f : -1e9f) + sy1.y;
            s[t][0] = v0; s[t][1] = v1; s[t][2] = v2; s[t][3] = v3;
            mx0 = fmaxf(mx0, fmaxf(v0, v1));
            mx1 = fmaxf(mx1, fmaxf(v2, v3));
        }
        mx0 = fmaxf(mx0, __shfl_xor_sync(0xffffffffu, mx0, 1));
        mx0 = fmaxf(mx0, __shfl_xor_sync(0xffffffffu, mx0, 2));
        mx1 = fmaxf(mx1, __shfl_xor_sync(0xffffffffu, mx1, 1));
        mx1 = fmaxf(mx1, __shfl_xor_sync(0xffffffffu, mx1, 2));
        if ((lane & 3) == 0) { redm[r * 16 + warp] = mx0; redm[(r + 8) * 16 + warp] = mx1; }
        __syncthreads();
        float gm0 = -1e30f, gm1 = -1e30f;
#pragma unroll
        for (int w = 0; w < 16; w++) {
            gm0 = fmaxf(gm0, redm[r * 16 + w]);
            gm1 = fmaxf(gm1, redm[(r + 8) * 16 + w]);
        }
        float su0 = 0.f, su1 = 0.f;
#pragma unroll
        for (int t = 0; t < 4; t++) {
            s[t][0] = __expf(s[t][0] - gm0); su0 += s[t][0];
            s[t][1] = __expf(s[t][1] - gm0); su0 += s[t][1];
            s[t][2] = __expf(s[t][2] - gm1); su1 += s[t][2];
            s[t][3] = __expf(s[t][3] - gm1); su1 += s[t][3];
        }
        su0 += __shfl_xor_sync(0xffffffffu, su0, 1);
        su0 += __shfl_xor_sync(0xffffffffu, su0, 2);
        su1 += __shfl_xor_sync(0xffffffffu, su1, 1);
        su1 += __shfl_xor_sync(0xffffffffu, su1, 2);
        if ((lane & 3) == 0) { reds[r * 16 + warp] = su0; reds[(r + 8) * 16 + warp] = su1; }
        __syncthreads();
        float gs0 = 0.f, gs1 = 0.f;
#pragma unroll
        for (int w = 0; w < 16; w++) { gs0 += reds[r * 16 + w]; gs1 += reds[(r + 8) * 16 + w]; }
        float i0 = 1.f / gs0, i1 = 1.f / gs1;
#pragma unroll
        for (int t = 0; t < 4; t++) {
            float a0 = s[t][0] * i0, a1 = s[t][1] * i0;
            float a2 = s[t][2] * i1, a3 = s[t][3] * i1;
            p1a[t][0] += a0; p1a[t][1] += a1; p1a[t][2] += a2; p1a[t][3] += a3;
            pca[t][0] += ch[h] * a0; pca[t][1] += ch[h] * a1;
            pca[t][2] += ch[h] * a2; pca[t][3] += ch[h] * a3;
        }
        __syncthreads();
    }
#pragma unroll
    for (int t = 0; t < 4; t++) {
        int col = n0 + 8 * t + cb;
        size_t o0 = ((size_t)(b * LL) + row0 + r    ) * LL + col;
        size_t o1 = ((size_t)(b * LL) + row0 + r + 8) * LL + col;
        *(half2*)&P1[o0] = __floats2half2_rn(p1a[t][0], p1a[t][1]);
        *(half2*)&P1[o1] = __floats2half2_rn(p1a[t][2], p1a[t][3]);
        *(half2*)&Pc[o0] = __floats2half2_rn(pca[t][0], pca[t][1]);
        *(half2*)&Pc[o1] = __floats2half2_rn(pca[t][2], pca[t][3]);
    }
}

// ---------------- fused GCN layer: mma P@X -> fp32 W-GEMM -> relu --------
__global__ __launch_bounds__(256) void layer_h(
    const __half* __restrict__ P,
    const __half* __restrict__ XT,
    const float* __restrict__ Ww, const float* __restrict__ Wb,
    __half* __restrict__ featsh, int off,
    float* __restrict__ x1f, __half* __restrict__ x1T,
    int mode,
    const float* __restrict__ V,
    const float* __restrict__ corrS,
    const float* __restrict__ pre)
{
    extern __shared__ float smf[];
    float* Axs = smf;                              // 64 x 104
    __half* hreg = (__half*)(smf + 64 * 104);
    __half* Pb[2] = { hreg,        hreg + 7040 };  // 64 x 40
    __half* Xb[2] = { hreg + 2560, hreg + 7040 + 2560 }; // 112 x 40
    float* Ws2 = smf + 64 * 104;                   // alias, phase 2: 100 x 116
    int bi = blockIdx.x * 64, b = blockIdx.y;
    int tid = threadIdx.x, lane = tid & 31, warp = tid >> 5;
    int wm = warp >> 1, wn = warp & 1;
    const __half* Pbase = P + (size_t)b * LL * LL;
    const __half* Xbase = XT + (size_t)b * LDQ * LL;
    for (int e = tid; e < 1024; e += 256) {
        int m = e >> 4, cp = e & 15;
        *(u32*)&Pb[0][m * 40 + 2 * cp] = *(const u32*)&Pbase[(size_t)(bi + m) * LL + 2 * cp];
    }
    for (int e = tid; e < 1792; e += 256) {
        int n = e >> 4, cp = e & 15;
        *(u32*)&Xb[0][n * 40 + 2 * cp] = *(const u32*)&Xbase[(size_t)n * LL + 2 * cp];
    }
    __syncthreads();
    float acc[7][4] = {};
    const int NIT = LL / 32;   // 16
    for (int it = 0; it < NIT; it++) {
        int cur = it & 1;
        u32 pa[4], pxb[7];
        if (it + 1 < NIT) {
            int k1 = (it + 1) * 32;
#pragma unroll
            for (int r2 = 0; r2 < 4; r2++) {
                int e = tid + 256 * r2, m = e >> 4, cp = e & 15;
                pa[r2] = *(const u32*)&Pbase[(size_t)(bi + m) * LL + k1 + 2 * cp];
            }
#pragma unroll
            for (int r2 = 0; r2 < 7; r2++) {
                int e = tid + 256 * r2, n = e >> 4, cp = e & 15;
                pxb[r2] = *(const u32*)&Xbase[(size_t)n * LL + k1 + 2 * cp];
            }
        }
        const __half* Ps = Pb[cur];
        const __half* Xs = Xb[cur];
#pragma unroll
        for (int ks = 0; ks < 32; ks += 16) {
            u32 a[4], bfr[2];
            ldfrag_a(a, Ps, wm * 16, ks, lane, 40);
#pragma unroll
            for (int t = 0; t < 7; t++) {
                ldfrag_b(bfr, Xs, wn * 56 + 8 * t, ks, lane, 40);
                mma_f16(acc[t], a, bfr);
            }
        }
        if (it + 1 < NIT) {
            __half* Pn = Pb[1 - cur];
            __half* Xn = Xb[1 - cur];
#pragma unroll
            for (int r2 = 0; r2 < 4; r2++) { int e = tid + 256 * r2; *(u32*)&Pn[(e >> 4) * 40 + 2 * (e & 15)] = pa[r2]; }
#pragma unroll
            for (int r2 = 0; r2 < 7; r2++) { int e = tid + 256 * r2; *(u32*)&Xn[(e >> 4) * 40 + 2 * (e & 15)] = pxb[r2]; }
        }
        __syncthreads();
    }
    int r = lane >> 2, cb = (lane & 3) * 2;
    float Cb = mode ? pre[204] : 0.f;
#pragma unroll
    for (int t = 0; t < 7; t++) {
        int col = wn * 56 + 8 * t + cb;
        if (col >= AA) continue;
        int rl0 = wm * 16 + r, rl1 = rl0 + 8;
        float v0 = acc[t][0], v1 = acc[t][1], v2 = acc[t][2], v3 = acc[t][3];
        if (mode) {
            float c0 = corrS[b * 2 * AA + col], c1 = corrS[b * 2 * AA + col + 1];
            float s0 = corrS[b * 2 * AA + AA + col], s1 = corrS[b * 2 * AA + AA + col + 1];
            float vr0 = V[b * LL + bi + rl0] + Cb;
            float vr1 = V[b * LL + bi + rl1] + Cb;
            v0 += c0 + vr0 * s0;  v1 += c1 + vr0 * s1;
            v2 += c0 + vr1 * s0;  v3 += c1 + vr1 * s1;
        }
        Axs[rl0 * 104 + col] = v0 * 0.25f;  Axs[rl0 * 104 + col + 1] = v1 * 0.25f;
        Axs[rl1 * 104 + col] = v2 * 0.25f;  Axs[rl1 * 104 + col + 1] = v3 * 0.25f;
    }
    for (int e = tid; e < AA * AA; e += 256) {
        int n = e / AA, kk = e % AA;
        Ws2[kk * 116 + n] = Ww[e];
    }
    for (int e = tid; e < AA * 16; e += 256) {
        int kk = e >> 4, n = AA + (e & 15);
        Ws2[kk * 116 + n] = 0.f;
    }
    __syncthreads();
    int tx = tid & 15, ty = tid >> 4;
    float acc2[4][7] = {};
#pragma unroll 4
    for (int kk = 0; kk < AA; kk++) {
        float a[4], w[7];
#pragma unroll
        for (int i = 0; i < 4; i++) a[i] = Axs[(ty + 16 * i) * 104 + kk];
#pragma unroll
        for (int j = 0; j < 7; j++) w[j] = Ws2[kk * 116 + tx + 16 * j];
#pragma unroll
        for (int i = 0; i < 4; i++)
#pragma unroll
            for (int j = 0; j < 7; j++)
                acc2[i][j] = fmaf(a[i], w[j], acc2[i][j]);
    }
#pragma unroll
    for (int i = 0; i < 4; i++) {
        int rowl = ty + 16 * i;
        size_t grow = (size_t)b * LL + bi + rowl;
#pragma unroll
        for (int j = 0; j < 7; j++) {
            int col = tx + 16 * j;
            if (col < AA) {
                float v = fmaxf(acc2[i][j] + Wb[col], 0.f);
                featsh[grow * LDFH + off + col] = __float2half(v);
                if (mode == 0) {
                    x1f[grow * AA + col] = v;
                    x1T[((size_t)b * LDQ + col) * LL + bi + rowl] = __float2half(v);
                }
            }
        }
    }
}

// ---------------- U, V per row ----------------
__global__ void uv_kernel(const float* __restrict__ x1,
                          const float* __restrict__ pre,
                          float* __restrict__ U, float* __restrict__ V)
{
    __shared__ float b1s[AA], b2s[AA];
    int tid = threadIdx.x;
    for (int e = tid; e < AA; e += 256) { b1s[e] = pre[4 + e]; b2s[e] = pre[104 + e]; }
    __syncthreads();
    int row = blockIdx.x * 8 + (tid >> 5);
    int lane = tid & 31;
    const float* xr = x1 + (size_t)row * AA;
    float u = 0.f, v = 0.f;
    for (int d = lane; d < AA; d += 32) {
        float xv = xr[d];
        u = fmaf(xv, b1s[d], u);
        v = fmaf(xv, b2s[d], v);
    }
    for (int o = 16; o; o >>= 1) {
        u += __shfl_xor_sync(0xffffffffu, u, o);
        v += __shfl_xor_sync(0xffffffffu, v, o);
    }
    if (lane == 0) { U[row] = u; V[row] = v; }
}

// ---------------- corr / S ----------------
__global__ void corrS_kernel(const float* __restrict__ x1,
                             const float* __restrict__ U,
                             float* __restrict__ corrS)
{
    __shared__ float sc[2][128], ss[2][128];
    int b = blockIdx.x, tid = threadIdx.x;
    int d = tid & 127, half = tid >> 7;
    float c = 0.f, s = 0.f;
    if (d < AA) {
        for (int j = half; j < LL; j += 2) {
            float xv = x1[((size_t)b * LL + j) * AA + d];
            c = fmaf(U[b * LL + j], xv, c);
            s += xv;
        }
    }
    sc[half][d] = c; ss[half][d] = s;
    __syncthreads();
    if (half == 0 && d < AA) {
        corrS[b * 2 * AA + d]      = sc[0][d] + sc[1][d];
        corrS[b * 2 * AA + AA + d] = ss[0][d] + ss[1][d];
    }
}

// ---------------- agg mma GEMM + relu + fused pool ----------------
__global__ __launch_bounds__(256) void agg_h(
    const __half* __restrict__ featsh,
    const float* __restrict__ W,      // agg_w, 100 x 300
    const float* __restrict__ bias,
    float* __restrict__ pool)
{
    extern __shared__ float smf[];
    float* red = smf;                          // 8 x 112
    __half* hreg = (__half*)(smf + 896);
    __half* Fb[2] = { hreg,        hreg + 7040 };
    __half* Bb[2] = { hreg + 2560, hreg + 7040 + 2560 };
    __shared__ float bsh[112];
    int bm = blockIdx.x * 64;
    int b = bm >> 9;
    int tid = threadIdx.x, lane = tid & 31, warp = tid >> 5;
    int wm = warp >> 1, wn = warp & 1;
    if (tid < 112) bsh[tid] = (tid < AA) ? bias[tid] : 0.f;
    // FIX: zero the reduction buffer (each warp only writes its 56-col half)
    for (int e = tid; e < 896; e += 256) red[e] = 0.f;
    // stage chunk 0
    for (int e = tid; e < 1024; e += 256) {
        int m = e >> 4, cp = e & 15;
        *(u32*)&Fb[0][m * 40 + 2 * cp] = *(const u32*)&featsh[(size_t)(bm + m) * LDFH + 2 * cp];
    }
    for (int e = tid; e < 1792; e += 256) {
        int n = e >> 4, cp = e & 15;
        int kk = 2 * cp;
        float w0 = (n < AA && kk     < 300) ? W[(size_t)n * 300 + kk]     : 0.f;
        float w1 = (n < AA && kk + 1 < 300) ? W[(size_t)n * 300 + kk + 1] : 0.f;
        *(half2*)&Bb[0][n * 40 + kk] = __floats2half2_rn(w0, w1);
    }
    __syncthreads();
    float acc[7][4] = {};
    const int NIT = 10;   // K = 320 (featsh cols 300..319 are zero)
    for (int it = 0; it < NIT; it++) {
        int cur = it & 1;
        u32 pf[4]; float pw0[7], pw1[7];
        if (it + 1 < NIT) {
            int k1 = (it + 1) * 32;
#pragma unroll
            for (int r2 = 0; r2 < 4; r2++) {
                int e = tid + 256 * r2, m = e >> 4, cp = e & 15;
                pf[r2] = *(const u32*)&featsh[(size_t)(bm + m) * LDFH + k1 + 2 * cp];
            }
#pragma unroll
            for (int r2 = 0; r2 < 7; r2++) {
                int e = tid + 256 * r2, n = e >> 4, cp = e & 15;
                int kk = k1 + 2 * cp;
                pw0[r2] = (n < AA && kk     < 300) ? W[(size_t)n * 300 + kk]     : 0.f;
                pw1[r2] = (n < AA && kk + 1 < 300) ? W[(size_t)n * 300 + kk + 1] : 0.f;
            }
        }
        const __half* Fs = Fb[cur];
        const __half* Bs = Bb[cur];
#pragma unroll
        for (int ks = 0; ks < 32; ks += 16) {
            u32 a[4], bfr[2];
            ldfrag_a(a, Fs, wm * 16, ks, lane, 40);
#pragma unroll
            for (int t = 0; t < 7; t++) {
                ldfrag_b(bfr, Bs, wn * 56 + 8 * t, ks, lane, 40);
                mma_f16(acc[t], a, bfr);
            }
        }
        if (it + 1 < NIT) {
            __half* Fn = Fb[1 - cur];
            __half* Bn = Bb[1 - cur];
#pragma unroll
            for (int r2 = 0; r2 < 4; r2++) { int e = tid + 256 * r2; *(u32*)&Fn[(e >> 4) * 40 + 2 * (e & 15)] = pf[r2]; }
#pragma unroll
            for (int r2 = 0; r2 < 7; r2++) { int e = tid + 256 * r2; *(half2*)&Bn[(e >> 4) * 40 + 2 * (e & 15)] = __floats2half2_rn(pw0[r2], pw1[r2]); }
        }
        __syncthreads();
    }
    // relu + column partial sums -> red -> pool
    int cb = (lane & 3) * 2;
#pragma unroll
    for (int t = 0; t < 7; t++) {
        int col = wn * 56 + 8 * t + cb;
        float s0 = fmaxf(acc[t][0] + bsh[col], 0.f)     + fmaxf(acc[t][2] + bsh[col], 0.f);
        float s1 = fmaxf(acc[t][1] + bsh[col + 1], 0.f) + fmaxf(acc[t][3] + bsh[col + 1], 0.f);
        s0 += __shfl_xor_sync(0xffffffffu, s0, 4);
        s0 += __shfl_xor_sync(0xffffffffu, s0, 8);
        s0 += __shfl_xor_sync(0xffffffffu, s0, 16);
        s1 += __shfl_xor_sync(0xffffffffu, s1, 4);
        s1 += __shfl_xor_sync(0xffffffffu, s1, 8);
        s1 += __shfl_xor_sync(0xffffffffu, s1, 16);
        if (lane < 4) {
            red[warp * 112 + col]     = s0;
            red[warp * 112 + col + 1] = s1;
        }
    }
    __syncthreads();
    if (tid < AA) {
        // FIX: only warps whose wn-half covers this column carry data (others zeroed)
        int w0 = (tid < 56) ? 0 : 1;
        float tot = 0.f;
#pragma unroll
        for (int w = 0; w < 4; w++) tot += red[(w0 + 2 * w) * 112 + tid];
        atomicAdd(&pool[b * AA + tid], tot);
    }
}

// ---------------- logits ----------------
__global__ void logits_kernel(const float* __restrict__ pool,
                              const int* __restrict__ mask_ids,
                              const float* __restrict__ cls_w,
                              const float* __restrict__ cls_b,
                              float* __restrict__ out)
{
    __shared__ float linv[BB];
    __shared__ float pr[BB * AA];
    __shared__ float cw[PP * AA];
    int tid = threadIdx.x;              // 512
    int warp = tid >> 5, lane = tid & 31;
    if (warp < BB) {
        int ms = 0;
#pragma unroll
        for (int t = 0; t < 16; t++) ms += mask_ids[warp * LL + lane + 32 * t];
        for (int o = 16; o; o >>= 1) ms += __shfl_xor_sync(0xffffffffu, ms, o);
        if (lane == 0) linv[warp] = 1.f / fmaxf((float)ms, 1.f);
    }
    for (int e = tid; e < BB * AA; e += 512) pr[e] = pool[e];
    for (int e = tid; e < PP * AA; e += 512) cw[e] = cls_w[e];
    __syncthreads();
    if (tid < BB * PP) {
        int b = tid / PP, p = tid % PP;
        float s0 = 0.f, s1 = 0.f, s2 = 0.f, s3 = 0.f;
#pragma unroll
        for (int d = 0; d < AA; d += 4) {
            s0 = fmaf(pr[b * AA + d + 0], cw[p * AA + d + 0], s0);
            s1 = fmaf(pr[b * AA + d + 1], cw[p * AA + d + 1], s1);
            s2 = fmaf(pr[b * AA + d + 2], cw[p * AA + d + 2], s2);
            s3 = fmaf(pr[b * AA + d + 3], cw[p * AA + d + 3], s3);
        }
        out[tid] = cls_b[p] + linv[b] * (s0 + s1 + s2 + s3);
    }
}

// ---------------- launch ----------------
extern "C" void kernel_launch(void* const* d_in, const int* in_sizes, int n_in,
                              void* d_out, int out_size)
{
    const float* seq      = (const float*)d_in[0];
    const float* syn      = (const float*)d_in[1];
    const float* ln_a     = (const float*)d_in[2];
    const float* ln_b     = (const float*)d_in[3];
    const float* Wxx_w    = (const float*)d_in[4];
    const float* Wxx_b    = (const float*)d_in[5];
    const float* q_w      = (const float*)d_in[6];
    const float* q_b      = (const float*)d_in[7];
    const float* k_w      = (const float*)d_in[8];
    const float* k_b      = (const float*)d_in[9];
    const float* W_w      = (const float*)d_in[10];
    const float* W_b      = (const float*)d_in[11];
    const float* Wx_w     = (const float*)d_in[12];
    const float* Wx_b     = (const float*)d_in[13];
    const float* agg_w    = (const float*)d_in[14];
    const float* agg_b    = (const float*)d_in[15];
    const float* cls_w    = (const float*)d_in[16];
    const float* cls_b    = (const float*)d_in[17];
    const int*   mask_ids = (const int*)d_in[18];
    const int*   src_mask = (const int*)d_in[19];
    float* out = (float*)d_out;

    __half *featsh, *xT, *x1T, *qh, *kh, *P1h, *Pch;
    float *x1f, *U, *V, *corrS, *pre, *pool, *mean, *inv;
    cudaGetSymbolAddress((void**)&featsh, g_featsh);
    cudaGetSymbolAddress((void**)&xT,     g_xT);
    cudaGetSymbolAddress((void**)&x1T,    g_x1T);
    cudaGetSymbolAddress((void**)&qh,     g_qh);
    cudaGetSymbolAddress((void**)&kh,     g_kh);
    cudaGetSymbolAddress((void**)&P1h,    g_P1h);
    cudaGetSymbolAddress((void**)&Pch,    g_Pch);
    cudaGetSymbolAddress((void**)&x1f,    g_x1);
    cudaGetSymbolAddress((void**)&U,      g_U);
    cudaGetSymbolAddress((void**)&V,      g_V);
    cudaGetSymbolAddress((void**)&corrS,  g_corrS);
    cudaGetSymbolAddress((void**)&pre,    g_pre);
    cudaGetSymbolAddress((void**)&pool,   g_pool);
    cudaGetSymbolAddress((void**)&mean,   g_mean);
    cudaGetSymbolAddress((void**)&inv,    g_inv);

    const int M = BB * LL;           // 8192
    const int GM = M / 64;           // 128

    const int GEMMLN_SMEM = 2 * 7040 * 2;                         // 28,160
    const int QK_SMEM     = (7680 + 2 * 13440) * 2;               // 69,120
    const int ATTN_SMEM   = 1024 * 4 + (512 * 40 + 16 * 40) * 2;  // 46,336
    const int LAYER_SMEM  = 64 * 104 * 4 + 100 * 116 * 4;         // 73,024
    const int AGG_SMEM    = 896 * 4 + 2 * 7040 * 2;               // 31,744
    cudaFuncSetAttribute(gemm_ln_h,   cudaFuncAttributeMaxDynamicSharedMemorySize, GEMMLN_SMEM);
    cudaFuncSetAttribute(qk_h,        cudaFuncAttributeMaxDynamicSharedMemorySize, QK_SMEM);
    cudaFuncSetAttribute(attn3_kernel,cudaFuncAttributeMaxDynamicSharedMemorySize, ATTN_SMEM);
    cudaFuncSetAttribute(layer_h,     cudaFuncAttributeMaxDynamicSharedMemorySize, LAYER_SMEM);
    cudaFuncSetAttribute(agg_h,       cudaFuncAttributeMaxDynamicSharedMemorySize, AGG_SMEM);

    // 0) folded weights + zero pool
    precomp_kernel<<<1, 256>>>(Wx_w, Wx_b, pre, pool);
    // 1) LN stats
    ln_stats<<<M / 8, 256>>>(seq, mean, inv);
    // 2) x = LN(seq) @ Wxx^T + b  -> featsh cols 0..99, xT
    gemm_ln_h<<<GM, 256, GEMMLN_SMEM>>>(seq, ln_a, ln_b, mean, inv, Wxx_w, Wxx_b, featsh, xT);
    // 3) q, k (half)
    qk_h<<<GM, 256, QK_SMEM>>>(featsh, q_w, q_b, k_w, k_b, qh, kh);
    // 4) attention -> P1h, Pch
    attn3_kernel<<<dim3(LL / 16, BB), 512, ATTN_SMEM>>>(qh, kh, syn, src_mask, pre, P1h, Pch);
    // 5) layer 1: x1 = relu((0.25*P1@x) @ W^T + b)
    layer_h<<<dim3(LL / 64, BB), 256, LAYER_SMEM>>>(P1h, xT, W_w, W_b, featsh, AA,
                                                    x1f, x1T, 0, nullptr, nullptr, pre);
    // 6) rank-1 corrections from x1
    uv_kernel<<<M / 8, 256>>>(x1f, pre, U, V);
    corrS_kernel<<<BB, 256>>>(x1f, U, corrS);
    // 7) layer 2: x2 = relu((0.25*(Pc@x1 + corr + (V+Cb)*S)) @ W^T + b)
    layer_h<<<dim3(LL / 64, BB), 256, LAYER_SMEM>>>(Pch, x1T, W_w, W_b, featsh, 2 * AA,
                                                    nullptr, nullptr, 1, V, corrS, pre);
    // 8) aggregate + relu + masked mean pool
    agg_h<<<GM, 256, AGG_SMEM>>>(featsh, agg_w, agg_b, pool);
    // 9) logits
    logits_kernel<<<1, 512>>>(pool, mask_ids, cls_w, cls_b, out);
}

// round 15
// speedup vs baseline: 3.1005x; 1.0231x over previous
#include <cuda_runtime.h>
#include <cuda_fp16.h>
#include <math.h>

constexpr int BB = 16, LL = 512, DD = 768, HH = 4, AA = 100, DKk = 25, PP = 3;
constexpr int LDW_X = HH + 2 * AA;     // 204
constexpr int LDQ  = 112;              // padded q/k row stride (4 heads x 28)
constexpr int HP   = 28;               // padded head dim
constexpr int LDFH = 320;              // featsh row stride (x|x1|x2|zeros)
constexpr float EPSf = 1e-6f;

using u32 = unsigned int;

// ---------------- device scratch (zero-initialized) ----------------
__device__ __align__(16) __half g_featsh[BB * LL * LDFH];  // cols 0-99 x,100-199 x1,200-299 x2
__device__ __align__(16) __half g_xT [BB * LDQ * LL];      // x^T  [b][d][j]
__device__ __align__(16) __half g_x1T[BB * LDQ * LL];
__device__ __align__(16) __half g_zp [BB * LL * LDQ];      // z, head-padded 28
__device__ __align__(16) __half g_kp [BB * LL * LDQ];      // x,  head-padded 28 (pads stay 0)
__device__ __align__(16) __half g_Mh [LDQ * LDQ];          // (Q^T K)^T padded, fp16
__device__ __align__(16) __half g_P1h[BB * LL * LL];       // sum_h adj_h      (8 MB)
__device__ __align__(16) __half g_Pch[BB * LL * LL];       // sum_h c_h adj_h  (8 MB)
__device__ float g_x1   [BB * LL * AA];                    // fp32 x1 for uv/corr
__device__ float g_U[BB * LL], g_V[BB * LL];
__device__ float g_corrS[BB * 2 * AA];
__device__ float g_pre[512];           // c[4] | b1s[100] | b2s[100] | Cb | w1[100]@208
__device__ float g_pool[BB * AA];

// ---------------- mma.sync m16n8k16 f16 helpers ----------------
__device__ __forceinline__ void mma_f16(float c[4], const u32 a[4], const u32 b[2])
{
    asm volatile(
        "mma.sync.aligned.m16n8k16.row.col.f32.f16.f16.f32 "
        "{%0,%1,%2,%3}, {%4,%5,%6,%7}, {%8,%9}, {%0,%1,%2,%3};\n"
        : "+f"(c[0]), "+f"(c[1]), "+f"(c[2]), "+f"(c[3])
        : "r"(a[0]), "r"(a[1]), "r"(a[2]), "r"(a[3]), "r"(b[0]), "r"(b[1]));
}
__device__ __forceinline__ void ldfrag_a(u32 a[4], const __half* S, int row0, int k0, int lane, int ld)
{
    int r = lane >> 2, c = (lane & 3) * 2;
    a[0] = *(const u32*)(S + (row0 + r    ) * ld + k0 + c    );
    a[1] = *(const u32*)(S + (row0 + r + 8) * ld + k0 + c    );
    a[2] = *(const u32*)(S + (row0 + r    ) * ld + k0 + c + 8);
    a[3] = *(const u32*)(S + (row0 + r + 8) * ld + k0 + c + 8);
}
__device__ __forceinline__ void ldfrag_b(u32 b[2], const __half* S, int n0, int k0, int lane, int ld)
{
    int r = lane >> 2, c = (lane & 3) * 2;
    b[0] = *(const u32*)(S + (n0 + r) * ld + k0 + c    );
    b[1] = *(const u32*)(S + (n0 + r) * ld + k0 + c + 8);
}

// ---------------- precompute: c, b1s, b2s, Cb, w1 + zero pool ------------
__global__ void precomp_kernel(const float* __restrict__ Wxw,
                               const float* __restrict__ Wxb,
                               const float* __restrict__ qb,
                               const float* __restrict__ kw,
                               float* __restrict__ pre, float* __restrict__ pool)
{
    int t = threadIdx.x;   // 512
    if (t < 4) {
        float s = 0.f;
        for (int g = 0; g < HH; g++) s += Wxw[g * LDW_X + t];
        pre[t] = s;
    } else if (t < 104) {
        int d = t - 4; float s = 0.f;
        for (int g = 0; g < HH; g++) s += Wxw[g * LDW_X + HH + d];
        pre[t] = s;
    } else if (t < 204) {
        int d = t - 104; float s = 0.f;
        for (int g = 0; g < HH; g++) s += Wxw[g * LDW_X + HH + AA + d];
        pre[t] = s;
    } else if (t == 204) {
        pre[204] = Wxb[0] + Wxb[1] + Wxb[2] + Wxb[3];
    } else if (t >= 208 && t < 208 + AA) {
        int e = t - 208; float s = 0.f;                 // w1 = K^T qb
        for (int n = 0; n < AA; n++) s = fmaf(qb[n], kw[n * AA + e], s);
        pre[t] = s;
    }
    for (int e = t; e < BB * AA; e += 512) pool[e] = 0.f;
}

// ---------------- M = (Q^T K)^T -> Mh[e][d] fp16, zero-padded ------------
__global__ void m_kernel(const float* __restrict__ qw, const float* __restrict__ kw,
                         __half* __restrict__ Mh)
{
    int idx = blockIdx.x * 256 + threadIdx.x;
    if (idx >= LDQ * LDQ) return;
    int e = idx / LDQ, d = idx % LDQ;
    float s = 0.f;
    if (e < AA && d < AA)
        for (int n = 0; n < AA; n++)
            s = fmaf(qw[n * AA + d], kw[n * AA + e], s);
    Mh[idx] = __float2half(s);
}

// ---------------- x = LN(seq) @ Wxx^T + b  (stats fused in-block) --------
__global__ __launch_bounds__(256) void gemm_ln_h(
    const float* __restrict__ seq,
    const float* __restrict__ ga, const float* __restrict__ gb,
    const float* __restrict__ W, const float* __restrict__ bias,
    __half* __restrict__ featsh, __half* __restrict__ xT,
    __half* __restrict__ kpad)
{
    extern __shared__ __half smh[];
    __half* Ab[2] = { smh,        smh + 7040 };        // 64x40
    __half* Bb[2] = { smh + 2560, smh + 7040 + 2560 }; // 112x40
    __shared__ float rmean[64], rinv[64], bsh[112];
    int bm = blockIdx.x * 64;
    int tid = threadIdx.x, lane = tid & 31, warp = tid >> 5;
    int wm = warp >> 1, wn = warp & 1;
    if (tid < 112) bsh[tid] = (tid < AA) ? bias[tid] : 0.f;
    // LN stats for this block's 64 rows (warp w -> rows 8w..8w+7)
    for (int rr = 0; rr < 8; rr++) {
        int row = warp * 8 + rr;
        const float4* xr = (const float4*)(seq + (size_t)(bm + row) * DD);
        float s = 0.f, s2 = 0.f;
#pragma unroll
        for (int d = lane; d < DD / 4; d += 32) {
            float4 v = xr[d];
            s += v.x + v.y + v.z + v.w;
            s2 = fmaf(v.x, v.x, s2); s2 = fmaf(v.y, v.y, s2);
            s2 = fmaf(v.z, v.z, s2); s2 = fmaf(v.w, v.w, s2);
        }
        for (int o = 16; o; o >>= 1) {
            s  += __shfl_xor_sync(0xffffffffu, s,  o);
            s2 += __shfl_xor_sync(0xffffffffu, s2, o);
        }
        if (lane == 0) {
            float m   = s / (float)DD;
            float var = (s2 - (float)DD * m * m) / (float)(DD - 1);
            rmean[row] = m;
            rinv[row]  = 1.f / (sqrtf(fmaxf(var, 0.f)) + EPSf);
        }
    }
    __syncthreads();
    // stage chunk 0
    for (int e = tid; e < 2048; e += 256) {
        int m = e >> 5, kk = e & 31;
        float v = seq[(size_t)(bm + m) * DD + kk];
        Ab[0][m * 40 + kk] = __float2half(fmaf(ga[kk], (v - rmean[m]) * rinv[m], gb[kk]));
    }
    for (int e = tid; e < 3584; e += 256) {
        int n = e >> 5, kk = e & 31;
        Bb[0][n * 40 + kk] = __float2half((n < AA) ? W[(size_t)n * DD + kk] : 0.f);
    }
    __syncthreads();
    float acc[7][4] = {};
    const int NIT = DD / 32;   // 24
    for (int it = 0; it < NIT; it++) {
        int cur = it & 1;
        float pa[8], pb[14];
        if (it + 1 < NIT) {
            int k1 = (it + 1) * 32;
#pragma unroll
            for (int r2 = 0; r2 < 8; r2++) {
                int e = tid + 256 * r2, m = e >> 5, kk = e & 31, kc = k1 + kk;
                float v = seq[(size_t)(bm + m) * DD + kc];
                pa[r2] = fmaf(ga[kc], (v - rmean[m]) * rinv[m], gb[kc]);
            }
#pragma unroll
            for (int r2 = 0; r2 < 14; r2++) {
                int e = tid + 256 * r2, n = e >> 5, kk = e & 31;
                pb[r2] = (n < AA) ? W[(size_t)n * DD + k1 + kk] : 0.f;
            }
        }
        const __half* As = Ab[cur];
        const __half* Bs = Bb[cur];
#pragma unroll
        for (int ks = 0; ks < 32; ks += 16) {
            u32 a[4], b[2];
            ldfrag_a(a, As, wm * 16, ks, lane, 40);
#pragma unroll
            for (int t = 0; t < 7; t++) {
                ldfrag_b(b, Bs, wn * 56 + 8 * t, ks, lane, 40);
                mma_f16(acc[t], a, b);
            }
        }
        if (it + 1 < NIT) {
            __half* An = Ab[1 - cur];
            __half* Bn = Bb[1 - cur];
#pragma unroll
            for (int r2 = 0; r2 < 8; r2++) { int e = tid + 256 * r2; An[(e >> 5) * 40 + (e & 31)] = __float2half(pa[r2]); }
#pragma unroll
            for (int r2 = 0; r2 < 14; r2++) { int e = tid + 256 * r2; Bn[(e >> 5) * 40 + (e & 31)] = __float2half(pb[r2]); }
        }
        __syncthreads();
    }
    int r = lane >> 2, cb = (lane & 3) * 2;
#pragma unroll
    for (int t = 0; t < 7; t++) {
        int col = wn * 56 + 8 * t + cb;
        if (col >= AA) continue;
        int g0 = bm + wm * 16 + r, g1 = g0 + 8;
        float o0 = acc[t][0] + bsh[col], o1 = acc[t][1] + bsh[col + 1];
        float o2 = acc[t][2] + bsh[col], o3 = acc[t][3] + bsh[col + 1];
        __half h0 = __float2half(o0), h1 = __float2half(o1);
        __half h2 = __float2half(o2), h3 = __float2half(o3);
        *(half2*)&featsh[(size_t)g0 * LDFH + col] = *(half2*)&h0, ((half2*)&featsh[(size_t)g0 * LDFH + col])->y = h1;
        featsh[(size_t)g0 * LDFH + col]     = h0;
        featsh[(size_t)g0 * LDFH + col + 1] = h1;
        featsh[(size_t)g1 * LDFH + col]     = h2;
        featsh[(size_t)g1 * LDFH + col + 1] = h3;
        int b0i = g0 >> 9, j0 = g0 & 511, b1i = g1 >> 9, j1 = g1 & 511;
        xT[((size_t)b0i * LDQ + col    ) * LL + j0] = h0;
        xT[((size_t)b0i * LDQ + col + 1) * LL + j0] = h1;
        xT[((size_t)b1i * LDQ + col    ) * LL + j1] = h2;
        xT[((size_t)b1i * LDQ + col + 1) * LL + j1] = h3;
        // head-padded layout for attention k-source
        int p0 = (col / 25) * HP + col % 25;
        int p1 = ((col + 1) / 25) * HP + (col + 1) % 25;
        kpad[(size_t)g0 * LDQ + p0] = h0;
        kpad[(size_t)g0 * LDQ + p1] = h1;
        kpad[(size_t)g1 * LDQ + p0] = h2;
        kpad[(size_t)g1 * LDQ + p1] = h3;
    }
}

// ---------------- z = x @ M + w1  (single GEMM replacing q AND k) --------
__global__ __launch_bounds__(256) void z_h(
    const __half* __restrict__ featsh,
    const __half* __restrict__ Mh,
    const float* __restrict__ pre,
    __half* __restrict__ zpad)
{
    extern __shared__ __half smh[];
    __half* Ash = smh;             // 64 x 120
    __half* Ws  = smh + 7680;      // 112 x 120
    __shared__ float bzs[112];
    int bm = blockIdx.x * 64;
    int tid = threadIdx.x, lane = tid & 31, warp = tid >> 5;
    int wm = warp >> 1, wn = warp & 1;
    if (tid < 112) bzs[tid] = (tid < AA) ? pre[208 + tid] : 0.f;
    for (int e = tid; e < 64 * 56; e += 256) {
        int m = e / 56, cp = e % 56;
        *(u32*)&Ash[m * 120 + 2 * cp] = *(const u32*)&featsh[(size_t)(bm + m) * LDFH + 2 * cp];
    }
    for (int e = tid; e < 112 * 56; e += 256) {
        int n = e / 56, cp = e % 56;
        *(u32*)&Ws[n * 120 + 2 * cp] = *(const u32*)&Mh[n * LDQ + 2 * cp];
    }
    __syncthreads();
    float az[7][4] = {};
#pragma unroll
    for (int ks = 0; ks < 7; ks++) {
        u32 a[4], b[2];
        ldfrag_a(a, Ash, wm * 16, 16 * ks, lane, 120);
#pragma unroll
        for (int t = 0; t < 7; t++) {
            ldfrag_b(b, Ws, wn * 56 + 8 * t, 16 * ks, lane, 120);
            mma_f16(az[t], a, b);
        }
    }
    int r = lane >> 2, cb = (lane & 3) * 2;
#pragma unroll
    for (int t = 0; t < 7; t++) {
        int col = wn * 56 + 8 * t + cb;
        if (col >= AA) continue;
        int g0 = bm + wm * 16 + r, g1 = g0 + 8;
        int p0 = (col / 25) * HP + col % 25;
        int p1 = ((col + 1) / 25) * HP + (col + 1) % 25;
        zpad[(size_t)g0 * LDQ + p0] = __float2half(az[t][0] + bzs[col]);
        zpad[(size_t)g0 * LDQ + p1] = __float2half(az[t][1] + bzs[col + 1]);
        zpad[(size_t)g1 * LDQ + p0] = __float2half(az[t][2] + bzs[col]);
        zpad[(size_t)g1 * LDQ + p1] = __float2half(az[t][3] + bzs[col + 1]);
    }
}

// ---------------- attention: scores = z . x  -> P1h, Pch ----------------
__global__ __launch_bounds__(512) void attn3_kernel(
    const __half* __restrict__ zpad, const __half* __restrict__ kpad,
    const float* __restrict__ syn, const int* __restrict__ src_mask,
    const float* __restrict__ pre,
    __half* __restrict__ P1, __half* __restrict__ Pc)
{
    extern __shared__ float smf[];
    float* mkf  = smf;          // 512
    float* redm = smf + 512;    // 16x16
    float* reds = smf + 768;    // 16x16
    __half* khs = (__half*)(smf + 1024);   // 512 x 40
    __half* qss = khs + 512 * 40;          // 16 x 40
    int itile = blockIdx.x, b = blockIdx.y;
    int tid = threadIdx.x, lane = tid & 31, warp = tid >> 5;
    int row0 = itile * 16;
    int n0 = warp * 32;
    int r = lane >> 2, cb = (lane & 3) * 2;

    mkf[tid] = src_mask[b * LL + tid] ? 1.f : 0.f;
    float ch[4] = { __ldg(pre), __ldg(pre + 1), __ldg(pre + 2), __ldg(pre + 3) };
    float p1a[4][4] = {}, pca[4][4] = {};

    for (int h = 0; h < HH; h++) {
        // vectorized k staging: 16 u32 per thread (head-padded source)
        for (int e = tid; e < 512 * 16; e += 512) {
            int j = e >> 4, cp = e & 15;
            u32 v = 0;
            if (cp < 14)
                v = *(const u32*)&kpad[(size_t)(b * LL + j) * LDQ + h * HP + 2 * cp];
            *(u32*)&khs[j * 40 + 2 * cp] = v;
        }
        {
            int j = tid >> 5, d = tid & 31;
            qss[j * 40 + d] = (d < DKk)
                ? zpad[(size_t)(b * LL + row0 + j) * LDQ + h * HP + d]
                : __float2half(0.f);
        }
        __syncthreads();
        float s[4][4] = {};
#pragma unroll
        for (int ks = 0; ks < 32; ks += 16) {
            u32 a[4], bfr[2];
            ldfrag_a(a, qss, 0, ks, lane, 40);
#pragma unroll
            for (int t = 0; t < 4; t++) {
                ldfrag_b(bfr, khs, n0 + 8 * t, ks, lane, 40);
                mma_f16(s[t], a, bfr);
            }
        }
        float mx0 = -1e30f, mx1 = -1e30f;
#pragma unroll
        for (int t = 0; t < 4; t++) {
            int col = n0 + 8 * t + cb;
            float2 sy0 = *(const float2*)&syn[(((size_t)(b * HH + h)) * LL + row0 + r    ) * LL + col];
            float2 sy1 = *(const float2*)&syn[(((size_t)(b * HH + h)) * LL + row0 + r + 8) * LL + col];
            float m0 = mkf[col], m1 = mkf[col + 1];
            float v0 = ((m0 != 0.f) ? s[t][0] * 0.2f : -1e9f) + sy0.x;
            float v1 = ((m1 != 0.f) ? s[t][1] * 0.2f : -1e9f) + sy0.y;
            float v2 = ((m0 != 0.f) ? s[t][2] * 0.2f : -1e9f) + sy1.x;
            float v3 = ((m1 != 0.f) ? s[t][3] * 0.2f : -1e9f) + sy1.y;
            s[t][0] = v0; s[t][1] = v1; s[t][2] = v2; s[t][3] = v3;
            mx0 = fmaxf(mx0, fmaxf(v0, v1));
            mx1 = fmaxf(mx1, fmaxf(v2, v3));
        }
        mx0 = fmaxf(mx0, __shfl_xor_sync(0xffffffffu, mx0, 1));
        mx0 = fmaxf(mx0, __shfl_xor_sync(0xffffffffu, mx0, 2));
        mx1 = fmaxf(mx1, __shfl_xor_sync(0xffffffffu, mx1, 1));
        mx1 = fmaxf(mx1, __shfl_xor_sync(0xffffffffu, mx1, 2));
        if ((lane & 3) == 0) { redm[r * 16 + warp] = mx0; redm[(r + 8) * 16 + warp] = mx1; }
        __syncthreads();
        float gm0 = -1e30f, gm1 = -1e30f;
#pragma unroll
        for (int w = 0; w < 16; w++) {
            gm0 = fmaxf(gm0, redm[r * 16 + w]);
            gm1 = fmaxf(gm1, redm[(r + 8) * 16 + w]);
        }
        float su0 = 0.f, su1 = 0.f;
#pragma unroll
        for (int t = 0; t < 4; t++) {
            s[t][0] = __expf(s[t][0] - gm0); su0 += s[t][0];
            s[t][1] = __expf(s[t][1] - gm0); su0 += s[t][1];
            s[t][2] = __expf(s[t][2] - gm1); su1 += s[t][2];
            s[t][3] = __expf(s[t][3] - gm1); su1 += s[t][3];
        }
        su0 += __shfl_xor_sync(0xffffffffu, su0, 1);
        su0 += __shfl_xor_sync(0xffffffffu, su0, 2);
        su1 += __shfl_xor_sync(0xffffffffu, su1, 1);
        su1 += __shfl_xor_sync(0xffffffffu, su1, 2);
        if ((lane & 3) == 0) { reds[r * 16 + warp] = su0; reds[(r + 8) * 16 + warp] = su1; }
        __syncthreads();
        float gs0 = 0.f, gs1 = 0.f;
#pragma unroll
        for (int w = 0; w < 16; w++) { gs0 += reds[r * 16 + w]; gs1 += reds[(r + 8) * 16 + w]; }
        float i0 = 1.f / gs0, i1 = 1.f / gs1;
#pragma unroll
        for (int t = 0; t < 4; t++) {
            float a0 = s[t][0] * i0, a1 = s[t][1] * i0;
            float a2 = s[t][2] * i1, a3 = s[t][3] * i1;
            p1a[t][0] += a0; p1a[t][1] += a1; p1a[t][2] += a2; p1a[t][3] += a3;
            pca[t][0] += ch[h] * a0; pca[t][1] += ch[h] * a1;
            pca[t][2] += ch[h] * a2; pca[t][3] += ch[h] * a3;
        }
        __syncthreads();
    }
#pragma unroll
    for (int t = 0; t < 4; t++) {
        int col = n0 + 8 * t + cb;
        size_t o0 = ((size_t)(b * LL) + row0 + r    ) * LL + col;
        size_t o1 = ((size_t)(b * LL) + row0 + r + 8) * LL + col;
        *(half2*)&P1[o0] = __floats2half2_rn(p1a[t][0], p1a[t][1]);
        *(half2*)&P1[o1] = __floats2half2_rn(p1a[t][2], p1a[t][3]);
        *(half2*)&Pc[o0] = __floats2half2_rn(pca[t][0], pca[t][1]);
        *(half2*)&Pc[o1] = __floats2half2_rn(pca[t][2], pca[t][3]);
    }
}

// ---------------- fused GCN layer: mma P@X -> fp32 W-GEMM -> relu --------
__global__ __launch_bounds__(256) void layer_h(
    const __half* __restrict__ P,
    const __half* __restrict__ XT,
    const float* __restrict__ Ww, const float* __restrict__ Wb,
    __half* __restrict__ featsh, int off,
    float* __restrict__ x1f, __half* __restrict__ x1T,
    int mode,
    const float* __restrict__ V,
    const float* __restrict__ corrS,
    const float* __restrict__ pre)
{
    extern __shared__ float smf[];
    float* Axs = smf;                              // 64 x 104
    __half* hreg = (__half*)(smf + 64 * 104);
    __half* Pb[2] = { hreg,        hreg + 7040 };  // 64 x 40
    __half* Xb[2] = { hreg + 2560, hreg + 7040 + 2560 }; // 112 x 40
    float* Ws2 = smf + 64 * 104;                   // alias, phase 2: 100 x 116
    int bi = blockIdx.x * 64, b = blockIdx.y;
    int tid = threadIdx.x, lane = tid & 31, warp = tid >> 5;
    int wm = warp >> 1, wn = warp & 1;
    const __half* Pbase = P + (size_t)b * LL * LL;
    const __half* Xbase = XT + (size_t)b * LDQ * LL;
    for (int e = tid; e < 1024; e += 256) {
        int m = e >> 4, cp = e & 15;
        *(u32*)&Pb[0][m * 40 + 2 * cp] = *(const u32*)&Pbase[(size_t)(bi + m) * LL + 2 * cp];
    }
    for (int e = tid; e < 1792; e += 256) {
        int n = e >> 4, cp = e & 15;
        *(u32*)&Xb[0][n * 40 + 2 * cp] = *(const u32*)&Xbase[(size_t)n * LL + 2 * cp];
    }
    __syncthreads();
    float acc[7][4] = {};
    const int NIT = LL / 32;   // 16
    for (int it = 0; it < NIT; it++) {
        int cur = it & 1;
        u32 pa[4], pxb[7];
        if (it + 1 < NIT) {
            int k1 = (it + 1) * 32;
#pragma unroll
            for (int r2 = 0; r2 < 4; r2++) {
                int e = tid + 256 * r2, m = e >> 4, cp = e & 15;
                pa[r2] = *(const u32*)&Pbase[(size_t)(bi + m) * LL + k1 + 2 * cp];
            }
#pragma unroll
            for (int r2 = 0; r2 < 7; r2++) {
                int e = tid + 256 * r2, n = e >> 4, cp = e & 15;
                pxb[r2] = *(const u32*)&Xbase[(size_t)n * LL + k1 + 2 * cp];
            }
        }
        const __half* Ps = Pb[cur];
        const __half* Xs = Xb[cur];
#pragma unroll
        for (int ks = 0; ks < 32; ks += 16) {
            u32 a[4], bfr[2];
            ldfrag_a(a, Ps, wm * 16, ks, lane, 40);
#pragma unroll
            for (int t = 0; t < 7; t++) {
                ldfrag_b(bfr, Xs, wn * 56 + 8 * t, ks, lane, 40);
                mma_f16(acc[t], a, bfr);
            }
        }
        if (it + 1 < NIT) {
            __half* Pn = Pb[1 - cur];
            __half* Xn = Xb[1 - cur];
#pragma unroll
            for (int r2 = 0; r2 < 4; r2++) { int e = tid + 256 * r2; *(u32*)&Pn[(e >> 4) * 40 + 2 * (e & 15)] = pa[r2]; }
#pragma unroll
            for (int r2 = 0; r2 < 7; r2++) { int e = tid + 256 * r2; *(u32*)&Xn[(e >> 4) * 40 + 2 * (e & 15)] = pxb[r2]; }
        }
        __syncthreads();
    }
    int r = lane >> 2, cb = (lane & 3) * 2;
    float Cb = mode ? pre[204] : 0.f;
#pragma unroll
    for (int t = 0; t < 7; t++) {
        int col = wn * 56 + 8 * t + cb;
        if (col >= AA) continue;
        int rl0 = wm * 16 + r, rl1 = rl0 + 8;
        float v0 = acc[t][0], v1 = acc[t][1], v2 = acc[t][2], v3 = acc[t][3];
        if (mode) {
            float c0 = corrS[b * 2 * AA + col], c1 = corrS[b * 2 * AA + col + 1];
            float s0 = corrS[b * 2 * AA + AA + col], s1 = corrS[b * 2 * AA + AA + col + 1];
            float vr0 = V[b * LL + bi + rl0] + Cb;
            float vr1 = V[b * LL + bi + rl1] + Cb;
            v0 += c0 + vr0 * s0;  v1 += c1 + vr0 * s1;
            v2 += c0 + vr1 * s0;  v3 += c1 + vr1 * s1;
        }
        Axs[rl0 * 104 + col] = v0 * 0.25f;  Axs[rl0 * 104 + col + 1] = v1 * 0.25f;
        Axs[rl1 * 104 + col] = v2 * 0.25f;  Axs[rl1 * 104 + col + 1] = v3 * 0.25f;
    }
    for (int e = tid; e < AA * AA; e += 256) {
        int n = e / AA, kk = e % AA;
        Ws2[kk * 116 + n] = Ww[e];
    }
    for (int e = tid; e < AA * 16; e += 256) {
        int kk = e >> 4, n = AA + (e & 15);
        Ws2[kk * 116 + n] = 0.f;
    }
    __syncthreads();
    int tx = tid & 15, ty = tid >> 4;
    float acc2[4][7] = {};
#pragma unroll 4
    for (int kk = 0; kk < AA; kk++) {
        float a[4], w[7];
#pragma unroll
        for (int i = 0; i < 4; i++) a[i] = Axs[(ty + 16 * i) * 104 + kk];
#pragma unroll
        for (int j = 0; j < 7; j++) w[j] = Ws2[kk * 116 + tx + 16 * j];
#pragma unroll
        for (int i = 0; i < 4; i++)
#pragma unroll
            for (int j = 0; j < 7; j++)
                acc2[i][j] = fmaf(a[i], w[j], acc2[i][j]);
    }
#pragma unroll
    for (int i = 0; i < 4; i++) {
        int rowl = ty + 16 * i;
        size_t grow = (size_t)b * LL + bi + rowl;
#pragma unroll
        for (int j = 0; j < 7; j++) {
            int col = tx + 16 * j;
            if (col < AA) {
                float v = fmaxf(acc2[i][j] + Wb[col], 0.f);
                featsh[grow * LDFH + off + col] = __float2half(v);
                if (mode == 0) {
                    x1f[grow * AA + col] = v;
                    x1T[((size_t)b * LDQ + col) * LL + bi + rowl] = __float2half(v);
                }
            }
        }
    }
}

// ---------------- U, V per row ----------------
__global__ void uv_kernel(const float* __restrict__ x1,
                          const float* __restrict__ pre,
                          float* __restrict__ U, float* __restrict__ V)
{
    __shared__ float b1s[AA], b2s[AA];
    int tid = threadIdx.x;
    for (int e = tid; e < AA; e += 256) { b1s[e] = pre[4 + e]; b2s[e] = pre[104 + e]; }
    __syncthreads();
    int row = blockIdx.x * 8 + (tid >> 5);
    int lane = tid & 31;
    const float* xr = x1 + (size_t)row * AA;
    float u = 0.f, v = 0.f;
    for (int d = lane; d < AA; d += 32) {
        float xv = xr[d];
        u = fmaf(xv, b1s[d], u);
        v = fmaf(xv, b2s[d], v);
    }
    for (int o = 16; o; o >>= 1) {
        u += __shfl_xor_sync(0xffffffffu, u, o);
        v += __shfl_xor_sync(0xffffffffu, v, o);
    }
    if (lane == 0) { U[row] = u; V[row] = v; }
}

// ---------------- corr / S ----------------
__global__ void corrS_kernel(const float* __restrict__ x1,
                             const float* __restrict__ U,
                             float* __restrict__ corrS)
{
    __shared__ float sc[2][128], ss[2][128];
    int b = blockIdx.x, tid = threadIdx.x;
    int d = tid & 127, half = tid >> 7;
    float c = 0.f, s = 0.f;
    if (d < AA) {
        for (int j = half; j < LL; j += 2) {
            float xv = x1[((size_t)b * LL + j) * AA + d];
            c = fmaf(U[b * LL + j], xv, c);
            s += xv;
        }
    }
    sc[half][d] = c; ss[half][d] = s;
    __syncthreads();
    if (half == 0 && d < AA) {
        corrS[b * 2 * AA + d]      = sc[0][d] + sc[1][d];
        corrS[b * 2 * AA + AA + d] = ss[0][d] + ss[1][d];
    }
}

// ---------------- agg mma GEMM + relu + fused pool ----------------
__global__ __launch_bounds__(256) void agg_h(
    const __half* __restrict__ featsh,
    const float* __restrict__ W,      // agg_w, 100 x 300
    const float* __restrict__ bias,
    float* __restrict__ pool)
{
    extern __shared__ float smf[];
    float* red = smf;                          // 8 x 112
    __half* hreg = (__half*)(smf + 896);
    __half* Fb[2] = { hreg,        hreg + 7040 };
    __half* Bb[2] = { hreg + 2560, hreg + 7040 + 2560 };
    __shared__ float bsh[112];
    int bm = blockIdx.x * 64;
    int b = bm >> 9;
    int tid = threadIdx.x, lane = tid & 31, warp = tid >> 5;
    int wm = warp >> 1, wn = warp & 1;
    if (tid < 112) bsh[tid] = (tid < AA) ? bias[tid] : 0.f;
    for (int e = tid; e < 896; e += 256) red[e] = 0.f;
    for (int e = tid; e < 1024; e += 256) {
        int m = e >> 4, cp = e & 15;
        *(u32*)&Fb[0][m * 40 + 2 * cp] = *(const u32*)&featsh[(size_t)(bm + m) * LDFH + 2 * cp];
    }
    for (int e = tid; e < 1792; e += 256) {
        int n = e >> 4, cp = e & 15;
        int kk = 2 * cp;
        float w0 = (n < AA && kk     < 300) ? W[(size_t)n * 300 + kk]     : 0.f;
        float w1 = (n < AA && kk + 1 < 300) ? W[(size_t)n * 300 + kk + 1] : 0.f;
        *(half2*)&Bb[0][n * 40 + kk] = __floats2half2_rn(w0, w1);
    }
    __syncthreads();
    float acc[7][4] = {};
    const int NIT = 10;
    for (int it = 0; it < NIT; it++) {
        int cur = it & 1;
        u32 pf[4]; float pw0[7], pw1[7];
        if (it + 1 < NIT) {
            int k1 = (it + 1) * 32;
#pragma unroll
            for (int r2 = 0; r2 < 4; r2++) {
                int e = tid + 256 * r2, m = e >> 4, cp = e & 15;
                pf[r2] = *(const u32*)&featsh[(size_t)(bm + m) * LDFH + k1 + 2 * cp];
            }
#pragma unroll
            for (int r2 = 0; r2 < 7; r2++) {
                int e = tid + 256 * r2, n = e >> 4, cp = e & 15;
                int kk = k1 + 2 * cp;
                pw0[r2] = (n < AA && kk     < 300) ? W[(size_t)n * 300 + kk]     : 0.f;
                pw1[r2] = (n < AA && kk + 1 < 300) ? W[(size_t)n * 300 + kk + 1] : 0.f;
            }
        }
        const __half* Fs = Fb[cur];
        const __half* Bs = Bb[cur];
#pragma unroll
        for (int ks = 0; ks < 32; ks += 16) {
            u32 a[4], bfr[2];
            ldfrag_a(a, Fs, wm * 16, ks, lane, 40);
#pragma unroll
            for (int t = 0; t < 7; t++) {
                ldfrag_b(bfr, Bs, wn * 56 + 8 * t, ks, lane, 40);
                mma_f16(acc[t], a, bfr);
            }
        }
        if (it + 1 < NIT) {
            __half* Fn = Fb[1 - cur];
            __half* Bn = Bb[1 - cur];
#pragma unroll
            for (int r2 = 0; r2 < 4; r2++) { int e = tid + 256 * r2; *(u32*)&Fn[(e >> 4) * 40 + 2 * (e & 15)] = pf[r2]; }
#pragma unroll
            for (int r2 = 0; r2 < 7; r2++) { int e = tid + 256 * r2; *(half2*)&Bn[(e >> 4) * 40 + 2 * (e & 15)] = __floats2half2_rn(pw0[r2], pw1[r2]); }
        }
        __syncthreads();
    }
    int cb = (lane & 3) * 2;
#pragma unroll
    for (int t = 0; t < 7; t++) {
        int col = wn * 56 + 8 * t + cb;
        float s0 = fmaxf(acc[t][0] + bsh[col], 0.f)     + fmaxf(acc[t][2] + bsh[col], 0.f);
        float s1 = fmaxf(acc[t][1] + bsh[col + 1], 0.f) + fmaxf(acc[t][3] + bsh[col + 1], 0.f);
        s0 += __shfl_xor_sync(0xffffffffu, s0, 4);
        s0 += __shfl_xor_sync(0xffffffffu, s0, 8);
        s0 += __shfl_xor_sync(0xffffffffu, s0, 16);
        s1 += __shfl_xor_sync(0xffffffffu, s1, 4);
        s1 += __shfl_xor_sync(0xffffffffu, s1, 8);
        s1 += __shfl_xor_sync(0xffffffffu, s1, 16);
        if (lane < 4) {
            red[warp * 112 + col]     = s0;
            red[warp * 112 + col + 1] = s1;
        }
    }
    __syncthreads();
    if (tid < AA) {
        int w0 = (tid < 56) ? 0 : 1;
        float tot = 0.f;
#pragma unroll
        for (int w = 0; w < 4; w++) tot += red[(w0 + 2 * w) * 112 + tid];
        atomicAdd(&pool[b * AA + tid], tot);
    }
}

// ---------------- logits ----------------
__global__ void logits_kernel(const float* __restrict__ pool,
                              const int* __restrict__ mask_ids,
                              const float* __restrict__ cls_w,
                              const float* __restrict__ cls_b,
                              float* __restrict__ out)
{
    __shared__ float linv[BB];
    __shared__ float pr[BB * AA];
    __shared__ float cw[PP * AA];
    int tid = threadIdx.x;              // 512
    int warp = tid >> 5, lane = tid & 31;
    if (warp < BB) {
        int ms = 0;
#pragma unroll
        for (int t = 0; t < 16; t++) ms += mask_ids[warp * LL + lane + 32 * t];
        for (int o = 16; o; o >>= 1) ms += __shfl_xor_sync(0xffffffffu, ms, o);
        if (lane == 0) linv[warp] = 1.f / fmaxf((float)ms, 1.f);
    }
    for (int e = tid; e < BB * AA; e += 512) pr[e] = pool[e];
    for (int e = tid; e < PP * AA; e += 512) cw[e] = cls_w[e];
    __syncthreads();
    if (tid < BB * PP) {
        int b = tid / PP, p = tid % PP;
        float s0 = 0.f, s1 = 0.f, s2 = 0.f, s3 = 0.f;
#pragma unroll
        for (int d = 0; d < AA; d += 4) {
            s0 = fmaf(pr[b * AA + d + 0], cw[p * AA + d + 0], s0);
            s1 = fmaf(pr[b * AA + d + 1], cw[p * AA + d + 1], s1);
            s2 = fmaf(pr[b * AA + d + 2], cw[p * AA + d + 2], s2);
            s3 = fmaf(pr[b * AA + d + 3], cw[p * AA + d + 3], s3);
        }
        out[tid] = cls_b[p] + linv[b] * (s0 + s1 + s2 + s3);
    }
}

// ---------------- launch ----------------
extern "C" void kernel_launch(void* const* d_in, const int* in_sizes, int n_in,
                              void* d_out, int out_size)
{
    const float* seq      = (const float*)d_in[0];
    const float* syn      = (const float*)d_in[1];
    const float* ln_a     = (const float*)d_in[2];
    const float* ln_b     = (const float*)d_in[3];
    const float* Wxx_w    = (const float*)d_in[4];
    const float* Wxx_b    = (const float*)d_in[5];
    const float* q_w      = (const float*)d_in[6];
    const float* q_b      = (const float*)d_in[7];
    const float* k_w      = (const float*)d_in[8];
    const float* k_b      = (const float*)d_in[9];
    const float* W_w      = (const float*)d_in[10];
    const float* W_b      = (const float*)d_in[11];
    const float* Wx_w     = (const float*)d_in[12];
    const float* Wx_b     = (const float*)d_in[13];
    const float* agg_w    = (const float*)d_in[14];
    const float* agg_b    = (const float*)d_in[15];
    const float* cls_w    = (const float*)d_in[16];
    const float* cls_b    = (const float*)d_in[17];
    const int*   mask_ids = (const int*)d_in[18];
    const int*   src_mask = (const int*)d_in[19];
    float* out = (float*)d_out;

    __half *featsh, *xT, *x1T, *zp, *kp, *Mh, *P1h, *Pch;
    float *x1f, *U, *V, *corrS, *pre, *pool;
    cudaGetSymbolAddress((void**)&featsh, g_featsh);
    cudaGetSymbolAddress((void**)&xT,     g_xT);
    cudaGetSymbolAddress((void**)&x1T,    g_x1T);
    cudaGetSymbolAddress((void**)&zp,     g_zp);
    cudaGetSymbolAddress((void**)&kp,     g_kp);
    cudaGetSymbolAddress((void**)&Mh,     g_Mh);
    cudaGetSymbolAddress((void**)&P1h,    g_P1h);
    cudaGetSymbolAddress((void**)&Pch,    g_Pch);
    cudaGetSymbolAddress((void**)&x1f,    g_x1);
    cudaGetSymbolAddress((void**)&U,      g_U);
    cudaGetSymbolAddress((void**)&V,      g_V);
    cudaGetSymbolAddress((void**)&corrS,  g_corrS);
    cudaGetSymbolAddress((void**)&pre,    g_pre);
    cudaGetSymbolAddress((void**)&pool,   g_pool);

    const int M = BB * LL;           // 8192
    const int GM = M / 64;           // 128

    const int GEMMLN_SMEM = 2 * 7040 * 2;                         // 28,160
    const int Z_SMEM      = (7680 + 13440) * 2;                   // 42,240
    const int ATTN_SMEM   = 1024 * 4 + (512 * 40 + 16 * 40) * 2;  // 46,336
    const int LAYER_SMEM  = 64 * 104 * 4 + 100 * 116 * 4;         // 73,024
    const int AGG_SMEM    = 896 * 4 + 2 * 7040 * 2;               // 31,744
    cudaFuncSetAttribute(gemm_ln_h,   cudaFuncAttributeMaxDynamicSharedMemorySize, GEMMLN_SMEM);
    cudaFuncSetAttribute(z_h,         cudaFuncAttributeMaxDynamicSharedMemorySize, Z_SMEM);
    cudaFuncSetAttribute(attn3_kernel,cudaFuncAttributeMaxDynamicSharedMemorySize, ATTN_SMEM);
    cudaFuncSetAttribute(layer_h,     cudaFuncAttributeMaxDynamicSharedMemorySize, LAYER_SMEM);
    cudaFuncSetAttribute(agg_h,       cudaFuncAttributeMaxDynamicSharedMemorySize, AGG_SMEM);

    // 0) folded weights (incl. w1 = K^T qb) + zero pool; M = (Q^T K)^T fp16
    precomp_kernel<<<1, 512>>>(Wx_w, Wx_b, q_b, k_w, pre, pool);
    m_kernel<<<(LDQ * LDQ + 255) / 256, 256>>>(q_w, k_w, Mh);
    // 1) x = LN(seq) @ Wxx^T + b  (stats in-block) -> featsh, xT, kpad
    gemm_ln_h<<<GM, 256, GEMMLN_SMEM>>>(seq, ln_a, ln_b, Wxx_w, Wxx_b, featsh, xT, kp);
    // 2) z = x @ M + w1 (replaces q AND k)
    z_h<<<GM, 256, Z_SMEM>>>(featsh, Mh, pre, zp);
    // 3) attention: scores = z . x -> P1h, Pch
    attn3_kernel<<<dim3(LL / 16, BB), 512, ATTN_SMEM>>>(zp, kp, syn, src_mask, pre, P1h, Pch);
    // 4) layer 1
    layer_h<<<dim3(LL / 64, BB), 256, LAYER_SMEM>>>(P1h, xT, W_w, W_b, featsh, AA,
                                                    x1f, x1T, 0, nullptr, nullptr, pre);
    // 5) rank-1 corrections
    uv_kernel<<<M / 8, 256>>>(x1f, pre, U, V);
    corrS_kernel<<<BB, 256>>>(x1f, U, corrS);
    // 6) layer 2
    layer_h<<<dim3(LL / 64, BB), 256, LAYER_SMEM>>>(Pch, x1T, W_w, W_b, featsh, 2 * AA,
                                                    nullptr, nullptr, 1, V, corrS, pre);
    // 7) aggregate + relu + masked mean pool
    agg_h<<<GM, 256, AGG_SMEM>>>(featsh, agg_w, agg_b, pool);
    // 8) logits
    logits_kernel<<<1, 512>>>(pool, mask_ids, cls_w, cls_b, out);
}